// round 2
// baseline (speedup 1.0000x reference)
#include <cuda_runtime.h>

#define HID    1024
#define SEQ    2048
#define BATCH  2
#define HEADS  16
#define HDIM   64
#define ROWS   (BATCH * SEQ)   // 4096

// ---------------- scratch (device globals; no allocations allowed) ----------
__device__ float g_xn[ROWS * HID];
__device__ float g_q [ROWS * HID];
__device__ float g_k [ROWS * HID];
__device__ float g_v [ROWS * HID];
__device__ float g_ctx[ROWS * HID];

// ---------------- LayerNorm: one block per row --------------------------------
__global__ __launch_bounds__(256) void ln_kernel(
    const float* __restrict__ x, const float* __restrict__ g,
    const float* __restrict__ b, float* __restrict__ xn)
{
    __shared__ float red[16];
    const int row = blockIdx.x;
    const int tid = threadIdx.x;
    const float4 v = *(const float4*)(x + (size_t)row * HID + tid * 4);

    float s1 = v.x + v.y + v.z + v.w;
    float s2 = v.x * v.x + v.y * v.y + v.z * v.z + v.w * v.w;
    #pragma unroll
    for (int off = 16; off; off >>= 1) {
        s1 += __shfl_xor_sync(0xffffffffu, s1, off);
        s2 += __shfl_xor_sync(0xffffffffu, s2, off);
    }
    const int warp = tid >> 5, lane = tid & 31;
    if (lane == 0) { red[warp] = s1; red[warp + 8] = s2; }
    __syncthreads();
    if (tid < 32) {
        float a  = (lane < 8) ? red[lane]     : 0.f;
        float b2 = (lane < 8) ? red[lane + 8] : 0.f;
        #pragma unroll
        for (int off = 4; off; off >>= 1) {
            a  += __shfl_xor_sync(0xffffffffu, a,  off);
            b2 += __shfl_xor_sync(0xffffffffu, b2, off);
        }
        if (lane == 0) { red[0] = a; red[1] = b2; }
    }
    __syncthreads();
    const float mu  = red[0] * (1.f / HID);
    const float var = red[1] * (1.f / HID) - mu * mu;
    const float rs  = rsqrtf(var + 1e-5f);

    const float4 gv = *(const float4*)(g + tid * 4);
    const float4 bv = *(const float4*)(b + tid * 4);
    float4 o;
    o.x = (v.x - mu) * rs * gv.x + bv.x;
    o.y = (v.y - mu) * rs * gv.y + bv.y;
    o.z = (v.z - mu) * rs * gv.z + bv.z;
    o.w = (v.w - mu) * rs * gv.w + bv.w;
    *(float4*)(xn + (size_t)row * HID + tid * 4) = o;
}

// ---------------- SGEMM: C[M,N] = A[M,K] @ W[N,K]^T + bias (+ resid) ----------
#define BM 64
#define BN 64
#define BK 16
#define LDT 68   // padded smem leading dim (float4-aligned, conflict-reducing)

__global__ __launch_bounds__(256) void sgemm_bias(
    const float* __restrict__ A, const float* __restrict__ W,
    const float* __restrict__ bias, const float* __restrict__ resid,
    float* __restrict__ C, int M, int N, int K)
{
    __shared__ float As[BK][LDT];
    __shared__ float Ws[BK][LDT];
    const int tid = threadIdx.x;
    const int tx = tid & 15, ty = tid >> 4;
    const int row0 = blockIdx.y * BM, col0 = blockIdx.x * BN;
    const int lrow = tid >> 2;           // 0..63
    const int lk   = (tid & 3) << 2;     // 0,4,8,12
    float acc[4][4] = {};

    const float* Ag = A + (size_t)(row0 + lrow) * K + lk;
    const float* Wg = W + (size_t)(col0 + lrow) * K + lk;

    for (int k0 = 0; k0 < K; k0 += BK) {
        const float4 a = *(const float4*)(Ag + k0);
        const float4 w = *(const float4*)(Wg + k0);
        __syncthreads();
        As[lk + 0][lrow] = a.x; As[lk + 1][lrow] = a.y;
        As[lk + 2][lrow] = a.z; As[lk + 3][lrow] = a.w;
        Ws[lk + 0][lrow] = w.x; Ws[lk + 1][lrow] = w.y;
        Ws[lk + 2][lrow] = w.z; Ws[lk + 3][lrow] = w.w;
        __syncthreads();
        #pragma unroll
        for (int kk = 0; kk < BK; kk++) {
            const float4 av = *(const float4*)&As[kk][ty << 2];
            const float4 wv = *(const float4*)&Ws[kk][tx << 2];
            acc[0][0] += av.x * wv.x; acc[0][1] += av.x * wv.y;
            acc[0][2] += av.x * wv.z; acc[0][3] += av.x * wv.w;
            acc[1][0] += av.y * wv.x; acc[1][1] += av.y * wv.y;
            acc[1][2] += av.y * wv.z; acc[1][3] += av.y * wv.w;
            acc[2][0] += av.z * wv.x; acc[2][1] += av.z * wv.y;
            acc[2][2] += av.z * wv.z; acc[2][3] += av.z * wv.w;
            acc[3][0] += av.w * wv.x; acc[3][1] += av.w * wv.y;
            acc[3][2] += av.w * wv.z; acc[3][3] += av.w * wv.w;
        }
    }
    const int cbase = col0 + (tx << 2);
    const float4 bv = *(const float4*)&bias[cbase];
    #pragma unroll
    for (int i = 0; i < 4; i++) {
        const int r = row0 + (ty << 2) + i;
        float4 o;
        o.x = acc[i][0] + bv.x; o.y = acc[i][1] + bv.y;
        o.z = acc[i][2] + bv.z; o.w = acc[i][3] + bv.w;
        if (resid) {
            const float4 rv = *(const float4*)&resid[(size_t)r * N + cbase];
            o.x += rv.x; o.y += rv.y; o.z += rv.z; o.w += rv.w;
        }
        *(float4*)&C[(size_t)r * N + cbase] = o;
    }
}

// ---------------- Flash attention: 64-query tile per block per (b,h) ----------
#define LDQ 68
#define SMEM_ATTN (3 * 64 * LDQ * 4)   // Qs + (Ks|Ps union) + Vs = 52224 B

__global__ __launch_bounds__(256) void attn_kernel(
    const float* __restrict__ Q, const float* __restrict__ K,
    const float* __restrict__ V, float* __restrict__ O)
{
    extern __shared__ float smem[];
    float* Qs  = smem;                 // [d][q], stride LDQ
    float* KPs = smem + 64 * LDQ;      // Ks[d][k] during scores, Ps[q][k] during PV
    float* Vs  = smem + 2 * 64 * LDQ;  // [k][d], stride LDQ

    const int tid = threadIdx.x;
    const int tx = tid & 15, ty = tid >> 4;
    const int q0 = blockIdx.x << 6;
    const int h  = blockIdx.y, b = blockIdx.z;
    const size_t base = (size_t)b * SEQ * HID + (size_t)h * HDIM;
    const float* Qb = Q + base;
    const float* Kb = K + base;
    const float* Vb = V + base;

    // load Q tile transposed: Qs[d][q]  (conflict-free smem stores)
    {
        const int r  = tid & 63;
        const int c0 = (tid >> 6) << 2;
        #pragma unroll
        for (int it = 0; it < 4; it++) {
            const int c = c0 + (it << 4);
            const float4 v = *(const float4*)&Qb[(size_t)(q0 + r) * HID + c];
            Qs[(c + 0) * LDQ + r] = v.x; Qs[(c + 1) * LDQ + r] = v.y;
            Qs[(c + 2) * LDQ + r] = v.z; Qs[(c + 3) * LDQ + r] = v.w;
        }
    }

    float m[4], l[4], o[4][4];
    #pragma unroll
    for (int i = 0; i < 4; i++) {
        m[i] = -1e30f; l[i] = 0.f;
        #pragma unroll
        for (int j = 0; j < 4; j++) o[i][j] = 0.f;
    }

    for (int k0 = 0; k0 < SEQ; k0 += 64) {
        __syncthreads();   // previous tile's PV reads done (and Q stores, iter 0)
        {   // K tile transposed into KPs[d][k]
            const int r  = tid & 63;
            const int c0 = (tid >> 6) << 2;
            #pragma unroll
            for (int it = 0; it < 4; it++) {
                const int c = c0 + (it << 4);
                const float4 kv = *(const float4*)&Kb[(size_t)(k0 + r) * HID + c];
                KPs[(c + 0) * LDQ + r] = kv.x; KPs[(c + 1) * LDQ + r] = kv.y;
                KPs[(c + 2) * LDQ + r] = kv.z; KPs[(c + 3) * LDQ + r] = kv.w;
            }
            // V tile natural: Vs[k][d] (coalesced global, vectorized smem)
            const int vr = tid >> 2;
            const int vc = (tid & 3) << 2;
            #pragma unroll
            for (int it = 0; it < 4; it++) {
                const int c = vc + (it << 4);
                *(float4*)&Vs[vr * LDQ + c] =
                    *(const float4*)&Vb[(size_t)(k0 + vr) * HID + c];
            }
        }
        __syncthreads();

        // S = Q K^T  (4x4 micro-tile per thread)
        float s[4][4] = {};
        #pragma unroll 8
        for (int d = 0; d < 64; d++) {
            const float4 qv = *(const float4*)&Qs [d * LDQ + (ty << 2)];
            const float4 kv = *(const float4*)&KPs[d * LDQ + (tx << 2)];
            s[0][0] += qv.x * kv.x; s[0][1] += qv.x * kv.y;
            s[0][2] += qv.x * kv.z; s[0][3] += qv.x * kv.w;
            s[1][0] += qv.y * kv.x; s[1][1] += qv.y * kv.y;
            s[1][2] += qv.y * kv.z; s[1][3] += qv.y * kv.w;
            s[2][0] += qv.z * kv.x; s[2][1] += qv.z * kv.y;
            s[2][2] += qv.z * kv.z; s[2][3] += qv.z * kv.w;
            s[3][0] += qv.w * kv.x; s[3][1] += qv.w * kv.y;
            s[3][2] += qv.w * kv.z; s[3][3] += qv.w * kv.w;
        }

        // online softmax (scale 1/sqrt(64) = 0.125)
        #pragma unroll
        for (int i = 0; i < 4; i++) {
            float mx = fmaxf(fmaxf(s[i][0] , s[i][1]), fmaxf(s[i][2], s[i][3]));
            mx *= 0.125f;
            mx = fmaxf(mx, __shfl_xor_sync(0xffffffffu, mx, 1));
            mx = fmaxf(mx, __shfl_xor_sync(0xffffffffu, mx, 2));
            mx = fmaxf(mx, __shfl_xor_sync(0xffffffffu, mx, 4));
            mx = fmaxf(mx, __shfl_xor_sync(0xffffffffu, mx, 8));
            const float mnew = fmaxf(m[i], mx);
            const float corr = __expf(m[i] - mnew);
            m[i] = mnew;
            float rs = 0.f;
            #pragma unroll
            for (int j = 0; j < 4; j++) {
                s[i][j] = __expf(s[i][j] * 0.125f - mnew);
                rs += s[i][j];
            }
            rs += __shfl_xor_sync(0xffffffffu, rs, 1);
            rs += __shfl_xor_sync(0xffffffffu, rs, 2);
            rs += __shfl_xor_sync(0xffffffffu, rs, 4);
            rs += __shfl_xor_sync(0xffffffffu, rs, 8);
            l[i] = l[i] * corr + rs;
            #pragma unroll
            for (int j = 0; j < 4; j++) o[i][j] *= corr;
        }

        __syncthreads();   // all Ks reads done before Ps overwrites the buffer
        #pragma unroll
        for (int i = 0; i < 4; i++) {
            float4 pv;
            pv.x = s[i][0]; pv.y = s[i][1]; pv.z = s[i][2]; pv.w = s[i][3];
            *(float4*)&KPs[((ty << 2) + i) * LDQ + (tx << 2)] = pv;
        }
        __syncthreads();

        // O += P V
        #pragma unroll 8
        for (int kk = 0; kk < 64; kk++) {
            const float4 vv = *(const float4*)&Vs[kk * LDQ + (tx << 2)];
            const float p0 = KPs[((ty << 2) + 0) * LDQ + kk];
            const float p1 = KPs[((ty << 2) + 1) * LDQ + kk];
            const float p2 = KPs[((ty << 2) + 2) * LDQ + kk];
            const float p3 = KPs[((ty << 2) + 3) * LDQ + kk];
            o[0][0] += p0 * vv.x; o[0][1] += p0 * vv.y;
            o[0][2] += p0 * vv.z; o[0][3] += p0 * vv.w;
            o[1][0] += p1 * vv.x; o[1][1] += p1 * vv.y;
            o[1][2] += p1 * vv.z; o[1][3] += p1 * vv.w;
            o[2][0] += p2 * vv.x; o[2][1] += p2 * vv.y;
            o[2][2] += p2 * vv.z; o[2][3] += p2 * vv.w;
            o[3][0] += p3 * vv.x; o[3][1] += p3 * vv.y;
            o[3][2] += p3 * vv.z; o[3][3] += p3 * vv.w;
        }
    }

    #pragma unroll
    for (int i = 0; i < 4; i++) {
        const float inv = 1.f / l[i];
        float4 ov;
        ov.x = o[i][0] * inv; ov.y = o[i][1] * inv;
        ov.z = o[i][2] * inv; ov.w = o[i][3] * inv;
        *(float4*)&O[base + (size_t)(q0 + (ty << 2) + i) * HID + (tx << 2)] = ov;
    }
}

// ---------------- launch -------------------------------------------------------
extern "C" void kernel_launch(void* const* d_in, const int* in_sizes, int n_in,
                              void* d_out, int out_size)
{
    const float* x    = (const float*)d_in[0];
    const float* Wq   = (const float*)d_in[1];
    const float* bq   = (const float*)d_in[2];
    const float* Wk   = (const float*)d_in[3];
    const float* bk   = (const float*)d_in[4];
    const float* Wv   = (const float*)d_in[5];
    const float* bv   = (const float*)d_in[6];
    const float* Wo   = (const float*)d_in[7];
    const float* bo   = (const float*)d_in[8];
    const float* ln_g = (const float*)d_in[9];
    const float* ln_b = (const float*)d_in[10];
    float* out = (float*)d_out;

    float *xn_p, *q_p, *k_p, *v_p, *ctx_p;
    cudaGetSymbolAddress((void**)&xn_p,  g_xn);
    cudaGetSymbolAddress((void**)&q_p,   g_q);
    cudaGetSymbolAddress((void**)&k_p,   g_k);
    cudaGetSymbolAddress((void**)&v_p,   g_v);
    cudaGetSymbolAddress((void**)&ctx_p, g_ctx);

    cudaFuncSetAttribute(attn_kernel,
        cudaFuncAttributeMaxDynamicSharedMemorySize, SMEM_ATTN);

    // 1) LayerNorm
    ln_kernel<<<ROWS, 256>>>(x, ln_g, ln_b, xn_p);

    // 2) QKV projections
    dim3 gg(HID / BN, ROWS / BM);
    sgemm_bias<<<gg, 256>>>(xn_p, Wq, bq, nullptr, q_p, ROWS, HID, HID);
    sgemm_bias<<<gg, 256>>>(xn_p, Wk, bk, nullptr, k_p, ROWS, HID, HID);
    sgemm_bias<<<gg, 256>>>(xn_p, Wv, bv, nullptr, v_p, ROWS, HID, HID);

    // 3) attention
    dim3 ag(SEQ / 64, HEADS, BATCH);
    attn_kernel<<<ag, 256, SMEM_ATTN>>>(q_p, k_p, v_p, ctx_p);

    // 4) output projection + bias + residual
    sgemm_bias<<<gg, 256>>>(ctx_p, Wo, bo, x, out, ROWS, HID, HID);
}

// round 3
// speedup vs baseline: 2.5665x; 2.5665x over previous
#include <cuda_runtime.h>
#include <cstdint>

#define HID    1024
#define SEQ    2048
#define BATCH  2
#define HEADS  16
#define HDIM   64
#define ROWS   (BATCH * SEQ)   // 4096

// ---------------- scratch (device globals; no allocations allowed) ----------
__device__ float g_xn[ROWS * HID];
__device__ float g_q [ROWS * HID];
__device__ float g_k [ROWS * HID];
__device__ float g_v [ROWS * HID];
__device__ float g_ctx[ROWS * HID];

// ---------------- helpers ----------------------------------------------------
__device__ __forceinline__ float tf32r(float x) {
    uint32_t u;
    asm("cvt.rna.tf32.f32 %0, %1;" : "=r"(u) : "f"(x));
    return __uint_as_float(u);
}

__device__ __forceinline__ void mma_tf32(float* c, const uint32_t* a, const uint32_t* b) {
    asm volatile(
        "mma.sync.aligned.m16n8k8.row.col.f32.tf32.tf32.f32 "
        "{%0,%1,%2,%3}, {%4,%5,%6,%7}, {%8,%9}, {%0,%1,%2,%3};"
        : "+f"(c[0]), "+f"(c[1]), "+f"(c[2]), "+f"(c[3])
        : "r"(a[0]), "r"(a[1]), "r"(a[2]), "r"(a[3]), "r"(b[0]), "r"(b[1]));
}

// ---------------- LayerNorm: one block per row --------------------------------
__global__ __launch_bounds__(256) void ln_kernel(
    const float* __restrict__ x, const float* __restrict__ g,
    const float* __restrict__ b, float* __restrict__ xn)
{
    __shared__ float red[16];
    const int row = blockIdx.x;
    const int tid = threadIdx.x;
    const float4 v = *(const float4*)(x + (size_t)row * HID + tid * 4);

    float s1 = v.x + v.y + v.z + v.w;
    float s2 = v.x * v.x + v.y * v.y + v.z * v.z + v.w * v.w;
    #pragma unroll
    for (int off = 16; off; off >>= 1) {
        s1 += __shfl_xor_sync(0xffffffffu, s1, off);
        s2 += __shfl_xor_sync(0xffffffffu, s2, off);
    }
    const int warp = tid >> 5, lane = tid & 31;
    if (lane == 0) { red[warp] = s1; red[warp + 8] = s2; }
    __syncthreads();
    if (tid < 32) {
        float a  = (lane < 8) ? red[lane]     : 0.f;
        float b2 = (lane < 8) ? red[lane + 8] : 0.f;
        #pragma unroll
        for (int off = 4; off; off >>= 1) {
            a  += __shfl_xor_sync(0xffffffffu, a,  off);
            b2 += __shfl_xor_sync(0xffffffffu, b2, off);
        }
        if (lane == 0) { red[0] = a; red[1] = b2; }
    }
    __syncthreads();
    const float mu  = red[0] * (1.f / HID);
    const float var = red[1] * (1.f / HID) - mu * mu;
    const float rs  = rsqrtf(var + 1e-5f);

    const float4 gv = *(const float4*)(g + tid * 4);
    const float4 bv = *(const float4*)(b + tid * 4);
    float4 o;
    o.x = (v.x - mu) * rs * gv.x + bv.x;
    o.y = (v.y - mu) * rs * gv.y + bv.y;
    o.z = (v.z - mu) * rs * gv.z + bv.z;
    o.w = (v.w - mu) * rs * gv.w + bv.w;
    *(float4*)(xn + (size_t)row * HID + tid * 4) = o;
}

// ---------------- TF32 mma GEMM: C[M,1024] = A @ W^T + bias (+resid) ----------
// 128x128x16 tile, 8 warps (2x4), warp tile 64x32, m16n8k8.
#define LDA 20   // smem leading dim: (m*20 + k) mod 32 hits all banks

__global__ __launch_bounds__(256, 2) void mma_gemm(
    const float* __restrict__ A, const float* __restrict__ W,
    const float* __restrict__ bias, const float* __restrict__ resid,
    float* __restrict__ C)
{
    __shared__ float As[128 * LDA];
    __shared__ float Ws[128 * LDA];
    const int tid  = threadIdx.x;
    const int lane = tid & 31;
    const int wid  = tid >> 5;
    const int wm   = (wid >> 2) * 64;   // warp row offset in tile
    const int wn   = (wid & 3) * 32;    // warp col offset in tile
    const int row0 = blockIdx.y * 128, col0 = blockIdx.x * 128;
    const int lr   = tid >> 2;          // 0..63
    const int lc   = (tid & 3) << 2;    // 0,4,8,12

    const float* Ag = A + (size_t)(row0 + lr) * HID + lc;
    const float* Wg = W + (size_t)(col0 + lr) * HID + lc;

    float4 pa0 = *(const float4*)Ag;
    float4 pa1 = *(const float4*)(Ag + 64 * HID);
    float4 pw0 = *(const float4*)Wg;
    float4 pw1 = *(const float4*)(Wg + 64 * HID);

    float acc[4][4][4];
    #pragma unroll
    for (int i = 0; i < 4; i++)
        #pragma unroll
        for (int j = 0; j < 4; j++)
            #pragma unroll
            for (int r = 0; r < 4; r++) acc[i][j][r] = 0.f;

    const int g  = lane >> 2;   // 0..7
    const int t4 = lane & 3;    // 0..3

    for (int kt = 0; kt < 64; kt++) {
        __syncthreads();
        {
            float4 t;
            t.x = tf32r(pa0.x); t.y = tf32r(pa0.y); t.z = tf32r(pa0.z); t.w = tf32r(pa0.w);
            *(float4*)&As[lr * LDA + lc] = t;
            t.x = tf32r(pa1.x); t.y = tf32r(pa1.y); t.z = tf32r(pa1.z); t.w = tf32r(pa1.w);
            *(float4*)&As[(lr + 64) * LDA + lc] = t;
            t.x = tf32r(pw0.x); t.y = tf32r(pw0.y); t.z = tf32r(pw0.z); t.w = tf32r(pw0.w);
            *(float4*)&Ws[lr * LDA + lc] = t;
            t.x = tf32r(pw1.x); t.y = tf32r(pw1.y); t.z = tf32r(pw1.z); t.w = tf32r(pw1.w);
            *(float4*)&Ws[(lr + 64) * LDA + lc] = t;
        }
        __syncthreads();
        if (kt < 63) {
            const int off = (kt + 1) * 16;
            pa0 = *(const float4*)(Ag + off);
            pa1 = *(const float4*)(Ag + 64 * HID + off);
            pw0 = *(const float4*)(Wg + off);
            pw1 = *(const float4*)(Wg + 64 * HID + off);
        }
        #pragma unroll
        for (int kk = 0; kk < 16; kk += 8) {
            const int kr = kk + t4;
            uint32_t af[4][4];
            #pragma unroll
            for (int mf = 0; mf < 4; mf++) {
                const int m = wm + mf * 16 + g;
                af[mf][0] = __float_as_uint(As[m * LDA + kr]);
                af[mf][1] = __float_as_uint(As[(m + 8) * LDA + kr]);
                af[mf][2] = __float_as_uint(As[m * LDA + kr + 4]);
                af[mf][3] = __float_as_uint(As[(m + 8) * LDA + kr + 4]);
            }
            uint32_t bf[4][2];
            #pragma unroll
            for (int nf = 0; nf < 4; nf++) {
                const int n = wn + nf * 8 + g;
                bf[nf][0] = __float_as_uint(Ws[n * LDA + kr]);
                bf[nf][1] = __float_as_uint(Ws[n * LDA + kr + 4]);
            }
            #pragma unroll
            for (int mf = 0; mf < 4; mf++)
                #pragma unroll
                for (int nf = 0; nf < 4; nf++)
                    mma_tf32(acc[mf][nf], af[mf], bf[nf]);
        }
    }

    // epilogue: c0/c1 -> (row, col..col+1), c2/c3 -> (row+8, ...)
    const int t2 = t4 * 2;
    #pragma unroll
    for (int mf = 0; mf < 4; mf++) {
        #pragma unroll
        for (int nf = 0; nf < 4; nf++) {
            const int r = row0 + wm + mf * 16 + g;
            const int c = col0 + wn + nf * 8 + t2;
            const float2 bb = *(const float2*)&bias[c];
            float2 o0 = { acc[mf][nf][0] + bb.x, acc[mf][nf][1] + bb.y };
            float2 o1 = { acc[mf][nf][2] + bb.x, acc[mf][nf][3] + bb.y };
            if (resid) {
                const float2 r0v = *(const float2*)&resid[(size_t)r * HID + c];
                const float2 r1v = *(const float2*)&resid[(size_t)(r + 8) * HID + c];
                o0.x += r0v.x; o0.y += r0v.y;
                o1.x += r1v.x; o1.y += r1v.y;
            }
            *(float2*)&C[(size_t)r * HID + c] = o0;
            *(float2*)&C[(size_t)(r + 8) * HID + c] = o1;
        }
    }
}

// ---------------- Flash attention with TF32 mma -------------------------------
// 128-query tile per block per (b,h); 8 warps, each owns a full 16x64 S strip.
#define LDS_ 68
#define SMEM_ATTN ((128 * LDS_ + 64 * LDS_ + 64 * LDS_ + 128 * LDS_) * 4)  // 104448

__global__ __launch_bounds__(256, 1) void attn_mma(
    const float* __restrict__ Q, const float* __restrict__ K,
    const float* __restrict__ V, float* __restrict__ O)
{
    extern __shared__ float sm[];
    float* Qs = sm;                                    // [128][68] row-major (q, d)
    float* Ks = sm + 128 * LDS_;                       // [64][68]  row-major (key, d)
    float* Vt = sm + (128 + 64) * LDS_;                // [64][68]  (d, key) -- V^T
    float* Ps = sm + (128 + 64 + 64) * LDS_;           // [128][68] (q, key)

    const int tid  = threadIdx.x;
    const int lane = tid & 31;
    const int wid  = tid >> 5;
    const int g    = lane >> 2;  // 0..7
    const int t4   = lane & 3;   // 0..3
    const int q0   = blockIdx.x << 7;
    const size_t base = (size_t)blockIdx.z * SEQ * HID + (size_t)blockIdx.y * HDIM;
    const float* Qb = Q + base;
    const float* Kb = K + base;
    const float* Vb = V + base;

    // load Q tile 128x64, tf32-rounded
    {
        const int c = (tid & 15) << 2;
        #pragma unroll
        for (int it = 0; it < 8; it++) {
            const int r = (tid >> 4) + it * 16;
            const float4 v = *(const float4*)&Qb[(size_t)(q0 + r) * HID + c];
            float4 t;
            t.x = tf32r(v.x); t.y = tf32r(v.y); t.z = tf32r(v.z); t.w = tf32r(v.w);
            *(float4*)&Qs[r * LDS_ + c] = t;
        }
    }

    float m0 = -1e30f, m1 = -1e30f, l0 = 0.f, l1 = 0.f;
    float oacc[8][4];
    #pragma unroll
    for (int nf = 0; nf < 8; nf++)
        #pragma unroll
        for (int j = 0; j < 4; j++) oacc[nf][j] = 0.f;

    const int rw = wid * 16 + g;   // this thread's row (and rw+8) within tile

    for (int kt = 0; kt < 32; kt++) {
        const int k0 = kt << 6;
        __syncthreads();   // prev iter's mma reads of Ks/Vt done (covers Q at kt=0)
        {
            const int c = (tid & 15) << 2;
            #pragma unroll
            for (int it = 0; it < 4; it++) {
                const int r = (tid >> 4) + it * 16;
                const float4 kv = *(const float4*)&Kb[(size_t)(k0 + r) * HID + c];
                float4 t;
                t.x = tf32r(kv.x); t.y = tf32r(kv.y); t.z = tf32r(kv.z); t.w = tf32r(kv.w);
                *(float4*)&Ks[r * LDS_ + c] = t;
                const float4 vv = *(const float4*)&Vb[(size_t)(k0 + r) * HID + c];
                Vt[(c + 0) * LDS_ + r] = tf32r(vv.x);
                Vt[(c + 1) * LDS_ + r] = tf32r(vv.y);
                Vt[(c + 2) * LDS_ + r] = tf32r(vv.z);
                Vt[(c + 3) * LDS_ + r] = tf32r(vv.w);
            }
        }
        __syncthreads();

        // S = Q K^T : warp strip 16x64
        float sacc[8][4];
        #pragma unroll
        for (int nf = 0; nf < 8; nf++)
            #pragma unroll
            for (int j = 0; j < 4; j++) sacc[nf][j] = 0.f;

        #pragma unroll
        for (int kk = 0; kk < 64; kk += 8) {
            const int kr = kk + t4;
            uint32_t a[4];
            a[0] = __float_as_uint(Qs[rw * LDS_ + kr]);
            a[1] = __float_as_uint(Qs[(rw + 8) * LDS_ + kr]);
            a[2] = __float_as_uint(Qs[rw * LDS_ + kr + 4]);
            a[3] = __float_as_uint(Qs[(rw + 8) * LDS_ + kr + 4]);
            #pragma unroll
            for (int nf = 0; nf < 8; nf++) {
                const int n = nf * 8 + g;
                uint32_t b[2];
                b[0] = __float_as_uint(Ks[n * LDS_ + kr]);
                b[1] = __float_as_uint(Ks[n * LDS_ + kr + 4]);
                mma_tf32(sacc[nf], a, b);
            }
        }

        // online softmax (scale 1/sqrt(64) = 0.125); rows rw and rw+8
        #pragma unroll
        for (int nf = 0; nf < 8; nf++)
            #pragma unroll
            for (int j = 0; j < 4; j++) sacc[nf][j] *= 0.125f;

        float mx0 = -1e30f, mx1 = -1e30f;
        #pragma unroll
        for (int nf = 0; nf < 8; nf++) {
            mx0 = fmaxf(mx0, fmaxf(sacc[nf][0], sacc[nf][1]));
            mx1 = fmaxf(mx1, fmaxf(sacc[nf][2], sacc[nf][3]));
        }
        mx0 = fmaxf(mx0, __shfl_xor_sync(0xffffffffu, mx0, 1));
        mx0 = fmaxf(mx0, __shfl_xor_sync(0xffffffffu, mx0, 2));
        mx1 = fmaxf(mx1, __shfl_xor_sync(0xffffffffu, mx1, 1));
        mx1 = fmaxf(mx1, __shfl_xor_sync(0xffffffffu, mx1, 2));

        const float mn0 = fmaxf(m0, mx0), mn1 = fmaxf(m1, mx1);
        const float corr0 = __expf(m0 - mn0), corr1 = __expf(m1 - mn1);
        m0 = mn0; m1 = mn1;

        float rs0 = 0.f, rs1 = 0.f;
        #pragma unroll
        for (int nf = 0; nf < 8; nf++) {
            sacc[nf][0] = __expf(sacc[nf][0] - mn0);
            sacc[nf][1] = __expf(sacc[nf][1] - mn0);
            sacc[nf][2] = __expf(sacc[nf][2] - mn1);
            sacc[nf][3] = __expf(sacc[nf][3] - mn1);
            rs0 += sacc[nf][0] + sacc[nf][1];
            rs1 += sacc[nf][2] + sacc[nf][3];
        }
        rs0 += __shfl_xor_sync(0xffffffffu, rs0, 1);
        rs0 += __shfl_xor_sync(0xffffffffu, rs0, 2);
        rs1 += __shfl_xor_sync(0xffffffffu, rs1, 1);
        rs1 += __shfl_xor_sync(0xffffffffu, rs1, 2);
        l0 = l0 * corr0 + rs0;
        l1 = l1 * corr1 + rs1;
        #pragma unroll
        for (int nf = 0; nf < 8; nf++) {
            oacc[nf][0] *= corr0; oacc[nf][1] *= corr0;
            oacc[nf][2] *= corr1; oacc[nf][3] *= corr1;
        }

        // write P strip (warp-private rows) to smem, tf32-rounded
        #pragma unroll
        for (int nf = 0; nf < 8; nf++) {
            const int c = nf * 8 + 2 * t4;
            float2 p0 = { tf32r(sacc[nf][0]), tf32r(sacc[nf][1]) };
            float2 p1 = { tf32r(sacc[nf][2]), tf32r(sacc[nf][3]) };
            *(float2*)&Ps[rw * LDS_ + c] = p0;
            *(float2*)&Ps[(rw + 8) * LDS_ + c] = p1;
        }
        __syncwarp();

        // O += P V : A from Ps, B from Vt (d x key)
        #pragma unroll
        for (int kk = 0; kk < 64; kk += 8) {
            const int kr = kk + t4;
            uint32_t a[4];
            a[0] = __float_as_uint(Ps[rw * LDS_ + kr]);
            a[1] = __float_as_uint(Ps[(rw + 8) * LDS_ + kr]);
            a[2] = __float_as_uint(Ps[rw * LDS_ + kr + 4]);
            a[3] = __float_as_uint(Ps[(rw + 8) * LDS_ + kr + 4]);
            #pragma unroll
            for (int nf = 0; nf < 8; nf++) {
                const int n = nf * 8 + g;
                uint32_t b[2];
                b[0] = __float_as_uint(Vt[n * LDS_ + kr]);
                b[1] = __float_as_uint(Vt[n * LDS_ + kr + 4]);
                mma_tf32(oacc[nf], a, b);
            }
        }
    }

    // epilogue
    const float inv0 = 1.f / l0, inv1 = 1.f / l1;
    #pragma unroll
    for (int nf = 0; nf < 8; nf++) {
        const int c = nf * 8 + 2 * t4;
        float2 o0 = { oacc[nf][0] * inv0, oacc[nf][1] * inv0 };
        float2 o1 = { oacc[nf][2] * inv1, oacc[nf][3] * inv1 };
        *(float2*)&O[base + (size_t)(q0 + rw) * HID + c] = o0;
        *(float2*)&O[base + (size_t)(q0 + rw + 8) * HID + c] = o1;
    }
}

// ---------------- launch -------------------------------------------------------
extern "C" void kernel_launch(void* const* d_in, const int* in_sizes, int n_in,
                              void* d_out, int out_size)
{
    const float* x    = (const float*)d_in[0];
    const float* Wq   = (const float*)d_in[1];
    const float* bq   = (const float*)d_in[2];
    const float* Wk   = (const float*)d_in[3];
    const float* bk   = (const float*)d_in[4];
    const float* Wv   = (const float*)d_in[5];
    const float* bv   = (const float*)d_in[6];
    const float* Wo   = (const float*)d_in[7];
    const float* bo   = (const float*)d_in[8];
    const float* ln_g = (const float*)d_in[9];
    const float* ln_b = (const float*)d_in[10];
    float* out = (float*)d_out;

    float *xn_p, *q_p, *k_p, *v_p, *ctx_p;
    cudaGetSymbolAddress((void**)&xn_p,  g_xn);
    cudaGetSymbolAddress((void**)&q_p,   g_q);
    cudaGetSymbolAddress((void**)&k_p,   g_k);
    cudaGetSymbolAddress((void**)&v_p,   g_v);
    cudaGetSymbolAddress((void**)&ctx_p, g_ctx);

    cudaFuncSetAttribute(attn_mma,
        cudaFuncAttributeMaxDynamicSharedMemorySize, SMEM_ATTN);

    // 1) LayerNorm
    ln_kernel<<<ROWS, 256>>>(x, ln_g, ln_b, xn_p);

    // 2) QKV projections (TF32 mma)
    dim3 gg(HID / 128, ROWS / 128);
    mma_gemm<<<gg, 256>>>(xn_p, Wq, bq, nullptr, q_p);
    mma_gemm<<<gg, 256>>>(xn_p, Wk, bk, nullptr, k_p);
    mma_gemm<<<gg, 256>>>(xn_p, Wv, bv, nullptr, v_p);

    // 3) attention (TF32 mma flash)
    dim3 ag(SEQ / 128, HEADS, BATCH);
    attn_mma<<<ag, 256, SMEM_ATTN>>>(q_p, k_p, v_p, ctx_p);

    // 4) output projection + bias + residual
    mma_gemm<<<gg, 256>>>(ctx_p, Wo, bo, x, out);
}

// round 4
// speedup vs baseline: 5.5323x; 2.1556x over previous
#include <cuda_runtime.h>
#include <cuda_bf16.h>
#include <cstdint>

#define HID    1024
#define SEQ    2048
#define BATCH  2
#define HEADS  16
#define HDIM   64
#define ROWS   (BATCH * SEQ)   // 4096

// ---------------- scratch (device globals; no allocations allowed) ----------
__device__ __nv_bfloat16 g_xn [ROWS * HID];
__device__ __nv_bfloat16 g_q  [ROWS * HID];
__device__ __nv_bfloat16 g_k  [ROWS * HID];
__device__ __nv_bfloat16 g_v  [ROWS * HID];
__device__ __nv_bfloat16 g_ctx[ROWS * HID];
__device__ __nv_bfloat16 g_wq [HID * HID];
__device__ __nv_bfloat16 g_wk [HID * HID];
__device__ __nv_bfloat16 g_wv [HID * HID];
__device__ __nv_bfloat16 g_wo [HID * HID];

// ---------------- helpers ----------------------------------------------------
__device__ __forceinline__ uint32_t smem_u32(const void* p) {
    return (uint32_t)__cvta_generic_to_shared(p);
}
__device__ __forceinline__ void cp16(uint32_t dst, const void* src) {
    asm volatile("cp.async.cg.shared.global [%0], [%1], 16;" :: "r"(dst), "l"(src));
}
#define CP_COMMIT() asm volatile("cp.async.commit_group;")
#define CP_WAIT0()  asm volatile("cp.async.wait_group 0;")

__device__ __forceinline__ void mma_bf16(float* c, const uint32_t* a, const uint32_t* b) {
    asm volatile(
        "mma.sync.aligned.m16n8k16.row.col.f32.bf16.bf16.f32 "
        "{%0,%1,%2,%3}, {%4,%5,%6,%7}, {%8,%9}, {%0,%1,%2,%3};"
        : "+f"(c[0]), "+f"(c[1]), "+f"(c[2]), "+f"(c[3])
        : "r"(a[0]), "r"(a[1]), "r"(a[2]), "r"(a[3]), "r"(b[0]), "r"(b[1]));
}
__device__ __forceinline__ void ldsm_x4_t(uint32_t* r, uint32_t addr) {
    asm volatile("ldmatrix.sync.aligned.m8n8.x4.trans.shared.b16 {%0,%1,%2,%3}, [%4];"
        : "=r"(r[0]), "=r"(r[1]), "=r"(r[2]), "=r"(r[3]) : "r"(addr));
}
__device__ __forceinline__ uint32_t ld32s(const __nv_bfloat16* p) {
    return *(const uint32_t*)p;
}
__device__ __forceinline__ uint32_t packbf(float lo, float hi) {
    __nv_bfloat162 t = __floats2bfloat162_rn(lo, hi);
    return *(uint32_t*)&t;
}

// ---------------- weight convert: fp32 -> bf16 --------------------------------
__global__ __launch_bounds__(256) void conv_kernel(
    const float4* __restrict__ src, __nv_bfloat162* __restrict__ dst)
{
    const int i = blockIdx.x * 256 + threadIdx.x;
    const float4 v = src[i];
    dst[2 * i + 0] = __floats2bfloat162_rn(v.x, v.y);
    dst[2 * i + 1] = __floats2bfloat162_rn(v.z, v.w);
}

// ---------------- LayerNorm: one block per row (bf16 out) ---------------------
__global__ __launch_bounds__(256) void ln_kernel(
    const float* __restrict__ x, const float* __restrict__ g,
    const float* __restrict__ b, __nv_bfloat16* __restrict__ xn)
{
    __shared__ float red[16];
    const int row = blockIdx.x;
    const int tid = threadIdx.x;
    const float4 v = *(const float4*)(x + (size_t)row * HID + tid * 4);

    float s1 = v.x + v.y + v.z + v.w;
    float s2 = v.x * v.x + v.y * v.y + v.z * v.z + v.w * v.w;
    #pragma unroll
    for (int off = 16; off; off >>= 1) {
        s1 += __shfl_xor_sync(0xffffffffu, s1, off);
        s2 += __shfl_xor_sync(0xffffffffu, s2, off);
    }
    const int warp = tid >> 5, lane = tid & 31;
    if (lane == 0) { red[warp] = s1; red[warp + 8] = s2; }
    __syncthreads();
    if (tid < 32) {
        float a  = (lane < 8) ? red[lane]     : 0.f;
        float b2 = (lane < 8) ? red[lane + 8] : 0.f;
        #pragma unroll
        for (int off = 4; off; off >>= 1) {
            a  += __shfl_xor_sync(0xffffffffu, a,  off);
            b2 += __shfl_xor_sync(0xffffffffu, b2, off);
        }
        if (lane == 0) { red[0] = a; red[1] = b2; }
    }
    __syncthreads();
    const float mu  = red[0] * (1.f / HID);
    const float var = red[1] * (1.f / HID) - mu * mu;
    const float rs  = rsqrtf(var + 1e-5f);

    const float4 gv = *(const float4*)(g + tid * 4);
    const float4 bv = *(const float4*)(b + tid * 4);
    __nv_bfloat162* o = (__nv_bfloat162*)(xn + (size_t)row * HID + tid * 4);
    o[0] = __floats2bfloat162_rn((v.x - mu) * rs * gv.x + bv.x,
                                 (v.y - mu) * rs * gv.y + bv.y);
    o[1] = __floats2bfloat162_rn((v.z - mu) * rs * gv.z + bv.z,
                                 (v.w - mu) * rs * gv.w + bv.w);
}

// ---------------- bf16 mma GEMM: C = A[M,K] @ W[N,K]^T + bias (+resid) --------
// 128x128x32 tile, 8 warps (2x4), warp tile 64x32, m16n8k16, cp.async 2-stage.
#define LDG_ 40                     // smem leading dim (halves): 80B rows
#define STG  (128 * LDG_)           // halves per stage

__global__ __launch_bounds__(256, 2) void mma_gemm(
    const __nv_bfloat16* __restrict__ A, const __nv_bfloat16* __restrict__ W,
    const float* __restrict__ bias, const float* __restrict__ resid,
    void* __restrict__ C, int out_fp32)
{
    __shared__ __nv_bfloat16 As[2 * STG];
    __shared__ __nv_bfloat16 Ws[2 * STG];
    const int tid  = threadIdx.x;
    const int lane = tid & 31;
    const int wid  = tid >> 5;
    const int wm   = (wid >> 2) * 64;
    const int wn   = (wid & 3) * 32;
    const int row0 = blockIdx.y * 128, col0 = blockIdx.x * 128;
    const int g    = lane >> 2;
    const int t4   = lane & 3;

    // cp.async fill mapping: row = tid>>1, two 16B chunks at (tid&1)*16 halves
    const int frow = tid >> 1;
    const int fcol = (tid & 1) * 16;
    const __nv_bfloat16* Agr = A + (size_t)(row0 + frow) * HID + fcol;
    const __nv_bfloat16* Wgr = W + (size_t)(col0 + frow) * HID + fcol;
    const uint32_t sA = smem_u32(As) + (frow * LDG_ + fcol) * 2;
    const uint32_t sW = smem_u32(Ws) + (frow * LDG_ + fcol) * 2;

    float acc[4][4][4];
    #pragma unroll
    for (int i = 0; i < 4; i++)
        #pragma unroll
        for (int j = 0; j < 4; j++)
            #pragma unroll
            for (int r = 0; r < 4; r++) acc[i][j][r] = 0.f;

    // prefetch stage 0
    cp16(sA, Agr);      cp16(sA + 16, Agr + 8);
    cp16(sW, Wgr);      cp16(sW + 16, Wgr + 8);
    CP_COMMIT();

    for (int kt = 0; kt < 32; kt++) {
        CP_WAIT0();
        __syncthreads();
        if (kt < 31) {
            const int k0 = (kt + 1) * 32;
            const uint32_t so = ((kt + 1) & 1) * STG * 2;
            cp16(sA + so, Agr + k0);      cp16(sA + so + 16, Agr + k0 + 8);
            cp16(sW + so, Wgr + k0);      cp16(sW + so + 16, Wgr + k0 + 8);
            CP_COMMIT();
        }
        const __nv_bfloat16* Ac = As + (kt & 1) * STG;
        const __nv_bfloat16* Wc = Ws + (kt & 1) * STG;
        #pragma unroll
        for (int kk = 0; kk < 32; kk += 16) {
            uint32_t af[4][4], bf[4][2];
            const int kb = kk + 2 * t4;
            #pragma unroll
            for (int mf = 0; mf < 4; mf++) {
                const int m = wm + mf * 16 + g;
                af[mf][0] = ld32s(&Ac[m * LDG_ + kb]);
                af[mf][1] = ld32s(&Ac[(m + 8) * LDG_ + kb]);
                af[mf][2] = ld32s(&Ac[m * LDG_ + kb + 8]);
                af[mf][3] = ld32s(&Ac[(m + 8) * LDG_ + kb + 8]);
            }
            #pragma unroll
            for (int nf = 0; nf < 4; nf++) {
                const int n = wn + nf * 8 + g;
                bf[nf][0] = ld32s(&Wc[n * LDG_ + kb]);
                bf[nf][1] = ld32s(&Wc[n * LDG_ + kb + 8]);
            }
            #pragma unroll
            for (int mf = 0; mf < 4; mf++)
                #pragma unroll
                for (int nf = 0; nf < 4; nf++)
                    mma_bf16(acc[mf][nf], af[mf], bf[nf]);
        }
    }

    const int t2 = t4 * 2;
    #pragma unroll
    for (int mf = 0; mf < 4; mf++) {
        #pragma unroll
        for (int nf = 0; nf < 4; nf++) {
            const int r = row0 + wm + mf * 16 + g;
            const int c = col0 + wn + nf * 8 + t2;
            const float2 bb = *(const float2*)&bias[c];
            float o00 = acc[mf][nf][0] + bb.x, o01 = acc[mf][nf][1] + bb.y;
            float o10 = acc[mf][nf][2] + bb.x, o11 = acc[mf][nf][3] + bb.y;
            if (out_fp32) {
                float* Cf = (float*)C;
                const float2 r0v = *(const float2*)&resid[(size_t)r * HID + c];
                const float2 r1v = *(const float2*)&resid[(size_t)(r + 8) * HID + c];
                float2 a0 = { o00 + r0v.x, o01 + r0v.y };
                float2 a1 = { o10 + r1v.x, o11 + r1v.y };
                *(float2*)&Cf[(size_t)r * HID + c] = a0;
                *(float2*)&Cf[(size_t)(r + 8) * HID + c] = a1;
            } else {
                __nv_bfloat16* Cb = (__nv_bfloat16*)C;
                *(uint32_t*)&Cb[(size_t)r * HID + c] = packbf(o00, o01);
                *(uint32_t*)&Cb[(size_t)(r + 8) * HID + c] = packbf(o10, o11);
            }
        }
    }
}

// ---------------- Flash attention, bf16 mma, cp.async 2-stage K/V -------------
// 128-query tile per block per (b,h); 8 warps, each owns a 16x64 S strip.
#define LDATT 72
#define KVST  (64 * LDATT)                // halves per K (or V) stage
// smem: QP(128*72) + Ks(2*64*72) + Vs(2*64*72)
#define SMEM_ATTN ((128 * LDATT + 4 * KVST) * 2)

__global__ __launch_bounds__(256, 2) void attn_mma(
    const __nv_bfloat16* __restrict__ Q, const __nv_bfloat16* __restrict__ K,
    const __nv_bfloat16* __restrict__ V, __nv_bfloat16* __restrict__ O)
{
    extern __shared__ __nv_bfloat16 sm[];
    __nv_bfloat16* QP = sm;                       // Q tile, later P tile
    __nv_bfloat16* Ks = sm + 128 * LDATT;         // 2 stages
    __nv_bfloat16* Vs = Ks + 2 * KVST;            // 2 stages

    const int tid  = threadIdx.x;
    const int lane = tid & 31;
    const int wid  = tid >> 5;
    const int g    = lane >> 2;
    const int t4   = lane & 3;
    const int q0   = blockIdx.x << 7;
    const size_t base = (size_t)blockIdx.z * SEQ * HID + (size_t)blockIdx.y * HDIM;
    const __nv_bfloat16* Qb = Q + base;
    const __nv_bfloat16* Kb = K + base;
    const __nv_bfloat16* Vb = V + base;
    const int rw = wid * 16 + g;

    const uint32_t sQP = smem_u32(QP);
    const uint32_t sK  = smem_u32(Ks);
    const uint32_t sV  = smem_u32(Vs);

    // ---- issue Q (128 rows x 64 halves) + K/V stage 0 (64 rows each) --------
    {   // Q: row = tid>>1, four 16B chunks at (tid&1)*32 halves
        const int r = tid >> 1, c = (tid & 1) * 32;
        const __nv_bfloat16* src = Qb + (size_t)(q0 + r) * HID + c;
        const uint32_t dst = sQP + (r * LDATT + c) * 2;
        cp16(dst, src); cp16(dst + 16, src + 8);
        cp16(dst + 32, src + 16); cp16(dst + 48, src + 24);
    }
    {   // K/V stage0: row = tid>>2, two 16B chunks at (tid&3)*16 halves
        const int r = tid >> 2, c = (tid & 3) * 16;
        const __nv_bfloat16* ksrc = Kb + (size_t)r * HID + c;
        const __nv_bfloat16* vsrc = Vb + (size_t)r * HID + c;
        const uint32_t kd = sK + (r * LDATT + c) * 2;
        const uint32_t vd = sV + (r * LDATT + c) * 2;
        cp16(kd, ksrc); cp16(kd + 16, ksrc + 8);
        cp16(vd, vsrc); cp16(vd + 16, vsrc + 8);
    }
    CP_COMMIT();
    CP_WAIT0();
    __syncthreads();

    // ---- hoist Q fragments to registers (rows rw, rw+8; all of d=64) --------
    uint32_t qf[4][4];
    #pragma unroll
    for (int k4 = 0; k4 < 4; k4++) {
        const int kb = k4 * 16 + 2 * t4;
        qf[k4][0] = ld32s(&QP[rw * LDATT + kb]);
        qf[k4][1] = ld32s(&QP[(rw + 8) * LDATT + kb]);
        qf[k4][2] = ld32s(&QP[rw * LDATT + kb + 8]);
        qf[k4][3] = ld32s(&QP[(rw + 8) * LDATT + kb + 8]);
    }
    __syncthreads();   // everyone read Q before QP becomes the P buffer

    float m0 = -1e30f, m1 = -1e30f, l0 = 0.f, l1 = 0.f;
    float oacc[8][4];
    #pragma unroll
    for (int nf = 0; nf < 8; nf++)
        #pragma unroll
        for (int j = 0; j < 4; j++) oacc[nf][j] = 0.f;

    for (int kt = 0; kt < 32; kt++) {
        CP_WAIT0();
        __syncthreads();
        if (kt < 31) {   // prefetch next K/V tile into other stage
            const int k0n = (kt + 1) << 6;
            const uint32_t so = ((kt + 1) & 1) * KVST * 2;
            const int r = tid >> 2, c = (tid & 3) * 16;
            const __nv_bfloat16* ksrc = Kb + (size_t)(k0n + r) * HID + c;
            const __nv_bfloat16* vsrc = Vb + (size_t)(k0n + r) * HID + c;
            const uint32_t kd = sK + so + (r * LDATT + c) * 2;
            const uint32_t vd = sV + so + (r * LDATT + c) * 2;
            cp16(kd, ksrc); cp16(kd + 16, ksrc + 8);
            cp16(vd, vsrc); cp16(vd + 16, vsrc + 8);
            CP_COMMIT();
        }
        const __nv_bfloat16* Kc = Ks + (kt & 1) * KVST;
        const uint32_t sVc = sV + (kt & 1) * KVST * 2;

        // ---- S = Q K^T : warp strip 16x64 -----------------------------------
        float sacc[8][4];
        #pragma unroll
        for (int nf = 0; nf < 8; nf++)
            #pragma unroll
            for (int j = 0; j < 4; j++) sacc[nf][j] = 0.f;

        #pragma unroll
        for (int k4 = 0; k4 < 4; k4++) {
            const int kb = k4 * 16 + 2 * t4;
            #pragma unroll
            for (int nf = 0; nf < 8; nf++) {
                const int n = nf * 8 + g;
                uint32_t b[2];
                b[0] = ld32s(&Kc[n * LDATT + kb]);
                b[1] = ld32s(&Kc[n * LDATT + kb + 8]);
                mma_bf16(sacc[nf], qf[k4], b);
            }
        }

        // ---- online softmax (scale 0.125) -----------------------------------
        #pragma unroll
        for (int nf = 0; nf < 8; nf++)
            #pragma unroll
            for (int j = 0; j < 4; j++) sacc[nf][j] *= 0.125f;

        float mx0 = -1e30f, mx1 = -1e30f;
        #pragma unroll
        for (int nf = 0; nf < 8; nf++) {
            mx0 = fmaxf(mx0, fmaxf(sacc[nf][0], sacc[nf][1]));
            mx1 = fmaxf(mx1, fmaxf(sacc[nf][2], sacc[nf][3]));
        }
        mx0 = fmaxf(mx0, __shfl_xor_sync(0xffffffffu, mx0, 1));
        mx0 = fmaxf(mx0, __shfl_xor_sync(0xffffffffu, mx0, 2));
        mx1 = fmaxf(mx1, __shfl_xor_sync(0xffffffffu, mx1, 1));
        mx1 = fmaxf(mx1, __shfl_xor_sync(0xffffffffu, mx1, 2));

        const float mn0 = fmaxf(m0, mx0), mn1 = fmaxf(m1, mx1);
        const float corr0 = __expf(m0 - mn0), corr1 = __expf(m1 - mn1);
        m0 = mn0; m1 = mn1;

        float rs0 = 0.f, rs1 = 0.f;
        #pragma unroll
        for (int nf = 0; nf < 8; nf++) {
            sacc[nf][0] = __expf(sacc[nf][0] - mn0);
            sacc[nf][1] = __expf(sacc[nf][1] - mn0);
            sacc[nf][2] = __expf(sacc[nf][2] - mn1);
            sacc[nf][3] = __expf(sacc[nf][3] - mn1);
            rs0 += sacc[nf][0] + sacc[nf][1];
            rs1 += sacc[nf][2] + sacc[nf][3];
        }
        rs0 += __shfl_xor_sync(0xffffffffu, rs0, 1);
        rs0 += __shfl_xor_sync(0xffffffffu, rs0, 2);
        rs1 += __shfl_xor_sync(0xffffffffu, rs1, 1);
        rs1 += __shfl_xor_sync(0xffffffffu, rs1, 2);
        l0 = l0 * corr0 + rs0;
        l1 = l1 * corr1 + rs1;
        #pragma unroll
        for (int nf = 0; nf < 8; nf++) {
            oacc[nf][0] *= corr0; oacc[nf][1] *= corr0;
            oacc[nf][2] *= corr1; oacc[nf][3] *= corr1;
        }

        // ---- P (bf16) into QP buffer; warp-private rows ---------------------
        #pragma unroll
        for (int nf = 0; nf < 8; nf++) {
            const int c = nf * 8 + 2 * t4;
            *(uint32_t*)&QP[rw * LDATT + c]       = packbf(sacc[nf][0], sacc[nf][1]);
            *(uint32_t*)&QP[(rw + 8) * LDATT + c] = packbf(sacc[nf][2], sacc[nf][3]);
        }
        __syncwarp();

        // ---- O += P V  (V via ldmatrix.x4.trans) ----------------------------
        #pragma unroll
        for (int k4 = 0; k4 < 4; k4++) {
            const int kk = k4 * 16;
            uint32_t a[4];
            const int kb = kk + 2 * t4;
            a[0] = ld32s(&QP[rw * LDATT + kb]);
            a[1] = ld32s(&QP[(rw + 8) * LDATT + kb]);
            a[2] = ld32s(&QP[rw * LDATT + kb + 8]);
            a[3] = ld32s(&QP[(rw + 8) * LDATT + kb + 8]);
            #pragma unroll
            for (int np = 0; np < 4; np++) {
                uint32_t r[4];
                const uint32_t addr = sVc +
                    ((kk + (lane & 15)) * LDATT + np * 16 + ((lane >> 4) << 3)) * 2;
                ldsm_x4_t(r, addr);
                mma_bf16(oacc[2 * np],     a, r);       // {r0,r1}
                mma_bf16(oacc[2 * np + 1], a, r + 2);   // {r2,r3}
            }
        }
    }

    // ---- epilogue (bf16 ctx) -------------------------------------------------
    const float inv0 = 1.f / l0, inv1 = 1.f / l1;
    #pragma unroll
    for (int nf = 0; nf < 8; nf++) {
        const int c = nf * 8 + 2 * t4;
        *(uint32_t*)&O[base + (size_t)(q0 + rw) * HID + c] =
            packbf(oacc[nf][0] * inv0, oacc[nf][1] * inv0);
        *(uint32_t*)&O[base + (size_t)(q0 + rw + 8) * HID + c] =
            packbf(oacc[nf][2] * inv1, oacc[nf][3] * inv1);
    }
}

// ---------------- launch -------------------------------------------------------
extern "C" void kernel_launch(void* const* d_in, const int* in_sizes, int n_in,
                              void* d_out, int out_size)
{
    const float* x    = (const float*)d_in[0];
    const float* Wq   = (const float*)d_in[1];
    const float* bq   = (const float*)d_in[2];
    const float* Wk   = (const float*)d_in[3];
    const float* bk   = (const float*)d_in[4];
    const float* Wv   = (const float*)d_in[5];
    const float* bv   = (const float*)d_in[6];
    const float* Wo   = (const float*)d_in[7];
    const float* bo   = (const float*)d_in[8];
    const float* ln_g = (const float*)d_in[9];
    const float* ln_b = (const float*)d_in[10];
    float* out = (float*)d_out;

    __nv_bfloat16 *xn_p, *q_p, *k_p, *v_p, *ctx_p, *wq_p, *wk_p, *wv_p, *wo_p;
    cudaGetSymbolAddress((void**)&xn_p,  g_xn);
    cudaGetSymbolAddress((void**)&q_p,   g_q);
    cudaGetSymbolAddress((void**)&k_p,   g_k);
    cudaGetSymbolAddress((void**)&v_p,   g_v);
    cudaGetSymbolAddress((void**)&ctx_p, g_ctx);
    cudaGetSymbolAddress((void**)&wq_p,  g_wq);
    cudaGetSymbolAddress((void**)&wk_p,  g_wk);
    cudaGetSymbolAddress((void**)&wv_p,  g_wv);
    cudaGetSymbolAddress((void**)&wo_p,  g_wo);

    cudaFuncSetAttribute(attn_mma,
        cudaFuncAttributeMaxDynamicSharedMemorySize, SMEM_ATTN);

    // 0) weight conversion fp32 -> bf16 (1M elems each -> 262144 float4)
    conv_kernel<<<1024, 256>>>((const float4*)Wq, (__nv_bfloat162*)wq_p);
    conv_kernel<<<1024, 256>>>((const float4*)Wk, (__nv_bfloat162*)wk_p);
    conv_kernel<<<1024, 256>>>((const float4*)Wv, (__nv_bfloat162*)wv_p);
    conv_kernel<<<1024, 256>>>((const float4*)Wo, (__nv_bfloat162*)wo_p);

    // 1) LayerNorm (bf16 out)
    ln_kernel<<<ROWS, 256>>>(x, ln_g, ln_b, xn_p);

    // 2) QKV projections (bf16 mma)
    dim3 gg(HID / 128, ROWS / 128);
    mma_gemm<<<gg, 256>>>(xn_p, wq_p, bq, nullptr, q_p, 0);
    mma_gemm<<<gg, 256>>>(xn_p, wk_p, bk, nullptr, k_p, 0);
    mma_gemm<<<gg, 256>>>(xn_p, wv_p, bv, nullptr, v_p, 0);

    // 3) attention (bf16 flash)
    dim3 ag(SEQ / 128, HEADS, BATCH);
    attn_mma<<<ag, 256, SMEM_ATTN>>>(q_p, k_p, v_p, ctx_p);

    // 4) output projection + bias + residual (fp32 out)
    mma_gemm<<<gg, 256>>>(ctx_p, wo_p, bo, x, out, 1);
}

// round 6
// speedup vs baseline: 6.5826x; 1.1899x over previous
#include <cuda_runtime.h>
#include <cuda_bf16.h>
#include <cstdint>

#define HID    1024
#define SEQ    2048
#define BATCH  2
#define HEADS  16
#define HDIM   64
#define ROWS   (BATCH * SEQ)   // 4096

// ---------------- scratch (device globals; no allocations allowed) ----------
__device__ __nv_bfloat16 g_xn  [ROWS * HID];
__device__ __nv_bfloat16 g_q   [ROWS * HID];
__device__ __nv_bfloat16 g_k   [ROWS * HID];
__device__ __nv_bfloat16 g_v   [ROWS * HID];
__device__ __nv_bfloat16 g_ctx [ROWS * HID];
__device__ __nv_bfloat16 g_wqkv[3 * HID * HID];
__device__ __nv_bfloat16 g_wo  [HID * HID];

// ---------------- helpers ----------------------------------------------------
__device__ __forceinline__ uint32_t smem_u32(const void* p) {
    return (uint32_t)__cvta_generic_to_shared(p);
}
__device__ __forceinline__ void cp16(uint32_t dst, const void* src) {
    asm volatile("cp.async.cg.shared.global [%0], [%1], 16;" :: "r"(dst), "l"(src));
}
#define CP_COMMIT() asm volatile("cp.async.commit_group;")
#define CP_WAIT0()  asm volatile("cp.async.wait_group 0;")
#define CP_WAIT1()  asm volatile("cp.async.wait_group 1;")

__device__ __forceinline__ void mma_bf16(float* c, const uint32_t* a, const uint32_t* b) {
    asm volatile(
        "mma.sync.aligned.m16n8k16.row.col.f32.bf16.bf16.f32 "
        "{%0,%1,%2,%3}, {%4,%5,%6,%7}, {%8,%9}, {%0,%1,%2,%3};"
        : "+f"(c[0]), "+f"(c[1]), "+f"(c[2]), "+f"(c[3])
        : "r"(a[0]), "r"(a[1]), "r"(a[2]), "r"(a[3]), "r"(b[0]), "r"(b[1]));
}
__device__ __forceinline__ void ldsm_x4(uint32_t* r, uint32_t addr) {
    asm volatile("ldmatrix.sync.aligned.m8n8.x4.shared.b16 {%0,%1,%2,%3}, [%4];"
        : "=r"(r[0]), "=r"(r[1]), "=r"(r[2]), "=r"(r[3]) : "r"(addr));
}
__device__ __forceinline__ void ldsm_x4_t(uint32_t* r, uint32_t addr) {
    asm volatile("ldmatrix.sync.aligned.m8n8.x4.trans.shared.b16 {%0,%1,%2,%3}, [%4];"
        : "=r"(r[0]), "=r"(r[1]), "=r"(r[2]), "=r"(r[3]) : "r"(addr));
}
__device__ __forceinline__ uint32_t ld32s(const __nv_bfloat16* p) {
    return *(const uint32_t*)p;
}
__device__ __forceinline__ uint32_t packbf(float lo, float hi) {
    __nv_bfloat162 t = __floats2bfloat162_rn(lo, hi);
    return *(uint32_t*)&t;
}

// ---------------- weight convert: fp32 -> bf16 --------------------------------
__global__ __launch_bounds__(256) void conv3_kernel(
    const float4* __restrict__ s0, const float4* __restrict__ s1,
    const float4* __restrict__ s2, __nv_bfloat162* __restrict__ dst)
{
    const int mat = blockIdx.y;
    const float4* src = (mat == 0) ? s0 : (mat == 1) ? s1 : s2;
    const int i = blockIdx.x * 256 + threadIdx.x;
    const float4 v = src[i];
    __nv_bfloat162* d = dst + (size_t)mat * (HID * HID / 2);
    d[2 * i + 0] = __floats2bfloat162_rn(v.x, v.y);
    d[2 * i + 1] = __floats2bfloat162_rn(v.z, v.w);
}
__global__ __launch_bounds__(256) void conv1_kernel(
    const float4* __restrict__ src, __nv_bfloat162* __restrict__ dst)
{
    const int i = blockIdx.x * 256 + threadIdx.x;
    const float4 v = src[i];
    dst[2 * i + 0] = __floats2bfloat162_rn(v.x, v.y);
    dst[2 * i + 1] = __floats2bfloat162_rn(v.z, v.w);
}

// ---------------- LayerNorm: one block per row (bf16 out) ---------------------
__global__ __launch_bounds__(256) void ln_kernel(
    const float* __restrict__ x, const float* __restrict__ g,
    const float* __restrict__ b, __nv_bfloat16* __restrict__ xn)
{
    __shared__ float red[16];
    const int row = blockIdx.x;
    const int tid = threadIdx.x;
    const float4 v = *(const float4*)(x + (size_t)row * HID + tid * 4);

    float s1 = v.x + v.y + v.z + v.w;
    float s2 = v.x * v.x + v.y * v.y + v.z * v.z + v.w * v.w;
    #pragma unroll
    for (int off = 16; off; off >>= 1) {
        s1 += __shfl_xor_sync(0xffffffffu, s1, off);
        s2 += __shfl_xor_sync(0xffffffffu, s2, off);
    }
    const int warp = tid >> 5, lane = tid & 31;
    if (lane == 0) { red[warp] = s1; red[warp + 8] = s2; }
    __syncthreads();
    if (tid < 32) {
        float a  = (lane < 8) ? red[lane]     : 0.f;
        float b2 = (lane < 8) ? red[lane + 8] : 0.f;
        #pragma unroll
        for (int off = 4; off; off >>= 1) {
            a  += __shfl_xor_sync(0xffffffffu, a,  off);
            b2 += __shfl_xor_sync(0xffffffffu, b2, off);
        }
        if (lane == 0) { red[0] = a; red[1] = b2; }
    }
    __syncthreads();
    const float mu  = red[0] * (1.f / HID);
    const float var = red[1] * (1.f / HID) - mu * mu;
    const float rs  = rsqrtf(var + 1e-5f);

    const float4 gv = *(const float4*)(g + tid * 4);
    const float4 bv = *(const float4*)(b + tid * 4);
    __nv_bfloat162* o = (__nv_bfloat162*)(xn + (size_t)row * HID + tid * 4);
    o[0] = __floats2bfloat162_rn((v.x - mu) * rs * gv.x + bv.x,
                                 (v.y - mu) * rs * gv.y + bv.y);
    o[1] = __floats2bfloat162_rn((v.z - mu) * rs * gv.z + bv.z,
                                 (v.w - mu) * rs * gv.w + bv.w);
}

// ---------------- bf16 mma GEMM (fused QKV or out-proj) -----------------------
// 128x128x32 tile, 8 warps (2x4), warp tile 64x32, m16n8k16,
// 3-stage cp.async pipeline, ldmatrix fragment loads.
#define LDG_ 40                     // smem leading dim in halves (80B rows)
#define STG  (128 * LDG_)

__global__ __launch_bounds__(256, 2) void mma_gemm(
    const __nv_bfloat16* __restrict__ A, const __nv_bfloat16* __restrict__ W,
    const float* __restrict__ b0p, const float* __restrict__ b1p,
    const float* __restrict__ b2p, const float* __restrict__ resid,
    __nv_bfloat16* __restrict__ C0, __nv_bfloat16* __restrict__ C1,
    __nv_bfloat16* __restrict__ C2, float* __restrict__ Cf, int out_fp32)
{
    __shared__ __nv_bfloat16 As[3 * STG];
    __shared__ __nv_bfloat16 Ws[3 * STG];
    const int tid  = threadIdx.x;
    const int lane = tid & 31;
    const int wid  = tid >> 5;
    const int wm   = (wid >> 2) * 64;
    const int wn   = (wid & 3) * 32;
    const int row0 = blockIdx.y * 128, col0 = blockIdx.x * 128;
    const int g    = lane >> 2;
    const int t4   = lane & 3;

    const int frow = tid >> 1;
    const int fcol = (tid & 1) * 16;
    const __nv_bfloat16* Agr = A + (size_t)(row0 + frow) * HID + fcol;
    const __nv_bfloat16* Wgr = W + (size_t)(col0 + frow) * HID + fcol;
    const uint32_t sAb = smem_u32(As) + (frow * LDG_ + fcol) * 2;
    const uint32_t sWb = smem_u32(Ws) + (frow * LDG_ + fcol) * 2;
    const uint32_t sA0 = smem_u32(As);
    const uint32_t sW0 = smem_u32(Ws);

    float acc[4][4][4];
    #pragma unroll
    for (int i = 0; i < 4; i++)
        #pragma unroll
        for (int j = 0; j < 4; j++)
            #pragma unroll
            for (int r = 0; r < 4; r++) acc[i][j][r] = 0.f;

    // prologue: stages 0 and 1
    #pragma unroll
    for (int s = 0; s < 2; s++) {
        const int k0 = s * 32;
        const uint32_t so = s * STG * 2;
        cp16(sAb + so, Agr + k0); cp16(sAb + so + 16, Agr + k0 + 8);
        cp16(sWb + so, Wgr + k0); cp16(sWb + so + 16, Wgr + k0 + 8);
        CP_COMMIT();
    }

    // ldmatrix lane addressing (within a stage)
    const int arow = (lane & 7) + ((lane >> 3) & 1) * 8;   // A: row offset
    const int akof = (lane >> 4) * 8;                      // A: k offset
    const int brow = (lane & 7) + ((lane >> 4) & 1) * 8;   // B: n offset
    const int bkof = ((lane >> 3) & 1) * 8;                // B: k offset

    for (int kt = 0; kt < 32; kt++) {
        if (kt < 30) { CP_WAIT1(); } else { CP_WAIT0(); }
        __syncthreads();
        if (kt < 30) {
            const int k0 = (kt + 2) * 32;
            const uint32_t so = ((kt + 2) % 3) * STG * 2;
            cp16(sAb + so, Agr + k0); cp16(sAb + so + 16, Agr + k0 + 8);
            cp16(sWb + so, Wgr + k0); cp16(sWb + so + 16, Wgr + k0 + 8);
            CP_COMMIT();
        }
        const uint32_t sAc = sA0 + (kt % 3) * STG * 2;
        const uint32_t sWc = sW0 + (kt % 3) * STG * 2;
        #pragma unroll
        for (int kk = 0; kk < 32; kk += 16) {
            uint32_t af[4][4], bf[2][4];
            #pragma unroll
            for (int mf = 0; mf < 4; mf++) {
                const int m = wm + mf * 16;
                ldsm_x4(af[mf], sAc + ((m + arow) * LDG_ + kk + akof) * 2);
            }
            #pragma unroll
            for (int nfp = 0; nfp < 2; nfp++) {
                const int n = wn + nfp * 16;
                ldsm_x4(bf[nfp], sWc + ((n + brow) * LDG_ + kk + bkof) * 2);
            }
            #pragma unroll
            for (int mf = 0; mf < 4; mf++)
                #pragma unroll
                for (int nfp = 0; nfp < 2; nfp++) {
                    mma_bf16(acc[mf][2 * nfp],     af[mf], bf[nfp]);
                    mma_bf16(acc[mf][2 * nfp + 1], af[mf], bf[nfp] + 2);
                }
        }
        if (kt >= 30) __syncthreads();   // keep last stages coherent (no new commit)
    }

    // epilogue
    const int sel  = col0 >> 10;
    const int colL = col0 & 1023;
    const float* bias = (sel == 0) ? b0p : (sel == 1) ? b1p : b2p;
    __nv_bfloat16* Cb = (sel == 0) ? C0 : (sel == 1) ? C1 : C2;
    const int t2 = t4 * 2;
    #pragma unroll
    for (int mf = 0; mf < 4; mf++) {
        #pragma unroll
        for (int nf = 0; nf < 4; nf++) {
            const int r = row0 + wm + mf * 16 + g;
            const int c = colL + wn + nf * 8 + t2;
            const float2 bb = *(const float2*)&bias[c];
            float o00 = acc[mf][nf][0] + bb.x, o01 = acc[mf][nf][1] + bb.y;
            float o10 = acc[mf][nf][2] + bb.x, o11 = acc[mf][nf][3] + bb.y;
            if (out_fp32) {
                const float2 r0v = *(const float2*)&resid[(size_t)r * HID + c];
                const float2 r1v = *(const float2*)&resid[(size_t)(r + 8) * HID + c];
                float2 a0 = { o00 + r0v.x, o01 + r0v.y };
                float2 a1 = { o10 + r1v.x, o11 + r1v.y };
                *(float2*)&Cf[(size_t)r * HID + c] = a0;
                *(float2*)&Cf[(size_t)(r + 8) * HID + c] = a1;
            } else {
                *(uint32_t*)&Cb[(size_t)r * HID + c] = packbf(o00, o01);
                *(uint32_t*)&Cb[(size_t)(r + 8) * HID + c] = packbf(o10, o11);
            }
        }
    }
}

// ---------------- Flash attention, bf16 mma, register P -----------------------
// 128-query tile per block per (b,h); 8 warps, each owns a 16x64 S strip.
#define LDATT 72
#define KVST  (64 * LDATT)
#define SMEM_ATTN ((128 * LDATT + 4 * KVST) * 2)   // 55296 B

__global__ __launch_bounds__(256, 2) void attn_mma(
    const __nv_bfloat16* __restrict__ Q, const __nv_bfloat16* __restrict__ K,
    const __nv_bfloat16* __restrict__ V, __nv_bfloat16* __restrict__ O)
{
    extern __shared__ __nv_bfloat16 sm[];
    __nv_bfloat16* QP = sm;
    __nv_bfloat16* Ks = sm + 128 * LDATT;
    __nv_bfloat16* Vs = Ks + 2 * KVST;

    const int tid  = threadIdx.x;
    const int lane = tid & 31;
    const int wid  = tid >> 5;
    const int g    = lane >> 2;
    const int t4   = lane & 3;
    const int q0   = blockIdx.x << 7;
    const size_t base = (size_t)blockIdx.z * SEQ * HID + (size_t)blockIdx.y * HDIM;
    const __nv_bfloat16* Qb = Q + base;
    const __nv_bfloat16* Kb = K + base;
    const __nv_bfloat16* Vb = V + base;
    const int rw = wid * 16 + g;

    const uint32_t sQP = smem_u32(QP);
    const uint32_t sK  = smem_u32(Ks);
    const uint32_t sV  = smem_u32(Vs);

    // issue Q + K/V stage 0
    {
        const int r = tid >> 1, c = (tid & 1) * 32;
        const __nv_bfloat16* src = Qb + (size_t)(q0 + r) * HID + c;
        const uint32_t dst = sQP + (r * LDATT + c) * 2;
        cp16(dst, src); cp16(dst + 16, src + 8);
        cp16(dst + 32, src + 16); cp16(dst + 48, src + 24);
    }
    {
        const int r = tid >> 2, c = (tid & 3) * 16;
        const __nv_bfloat16* ksrc = Kb + (size_t)r * HID + c;
        const __nv_bfloat16* vsrc = Vb + (size_t)r * HID + c;
        const uint32_t kd = sK + (r * LDATT + c) * 2;
        const uint32_t vd = sV + (r * LDATT + c) * 2;
        cp16(kd, ksrc); cp16(kd + 16, ksrc + 8);
        cp16(vd, vsrc); cp16(vd + 16, vsrc + 8);
    }
    CP_COMMIT();
    CP_WAIT0();
    __syncthreads();

    // hoist Q fragments
    uint32_t qf[4][4];
    #pragma unroll
    for (int k4 = 0; k4 < 4; k4++) {
        const int kb = k4 * 16 + 2 * t4;
        qf[k4][0] = ld32s(&QP[rw * LDATT + kb]);
        qf[k4][1] = ld32s(&QP[(rw + 8) * LDATT + kb]);
        qf[k4][2] = ld32s(&QP[rw * LDATT + kb + 8]);
        qf[k4][3] = ld32s(&QP[(rw + 8) * LDATT + kb + 8]);
    }

    float m0 = -1e30f, m1 = -1e30f, l0 = 0.f, l1 = 0.f;
    float oacc[8][4];
    #pragma unroll
    for (int nf = 0; nf < 8; nf++)
        #pragma unroll
        for (int j = 0; j < 4; j++) oacc[nf][j] = 0.f;

    // ldmatrix lane addressing for K (B-operand)
    const int brow = (lane & 7) + ((lane >> 4) & 1) * 8;
    const int bkof = ((lane >> 3) & 1) * 8;

    for (int kt = 0; kt < 32; kt++) {
        CP_WAIT0();
        __syncthreads();
        if (kt < 31) {
            const int k0n = (kt + 1) << 6;
            const uint32_t so = ((kt + 1) & 1) * KVST * 2;
            const int r = tid >> 2, c = (tid & 3) * 16;
            const __nv_bfloat16* ksrc = Kb + (size_t)(k0n + r) * HID + c;
            const __nv_bfloat16* vsrc = Vb + (size_t)(k0n + r) * HID + c;
            const uint32_t kd = sK + so + (r * LDATT + c) * 2;
            const uint32_t vd = sV + so + (r * LDATT + c) * 2;
            cp16(kd, ksrc); cp16(kd + 16, ksrc + 8);
            cp16(vd, vsrc); cp16(vd + 16, vsrc + 8);
            CP_COMMIT();
        }
        const uint32_t sKc = sK + (kt & 1) * KVST * 2;
        const uint32_t sVc = sV + (kt & 1) * KVST * 2;

        // S = Q K^T
        float sacc[8][4];
        #pragma unroll
        for (int nf = 0; nf < 8; nf++)
            #pragma unroll
            for (int j = 0; j < 4; j++) sacc[nf][j] = 0.f;

        #pragma unroll
        for (int k4 = 0; k4 < 4; k4++) {
            const int kb0 = k4 * 16;
            #pragma unroll
            for (int nfp = 0; nfp < 4; nfp++) {
                uint32_t bfr[4];
                ldsm_x4(bfr, sKc + ((nfp * 16 + brow) * LDATT + kb0 + bkof) * 2);
                mma_bf16(sacc[2 * nfp],     qf[k4], bfr);
                mma_bf16(sacc[2 * nfp + 1], qf[k4], bfr + 2);
            }
        }

        // online softmax (scale 0.125)
        #pragma unroll
        for (int nf = 0; nf < 8; nf++)
            #pragma unroll
            for (int j = 0; j < 4; j++) sacc[nf][j] *= 0.125f;

        float mx0 = -1e30f, mx1 = -1e30f;
        #pragma unroll
        for (int nf = 0; nf < 8; nf++) {
            mx0 = fmaxf(mx0, fmaxf(sacc[nf][0], sacc[nf][1]));
            mx1 = fmaxf(mx1, fmaxf(sacc[nf][2], sacc[nf][3]));
        }
        mx0 = fmaxf(mx0, __shfl_xor_sync(0xffffffffu, mx0, 1));
        mx0 = fmaxf(mx0, __shfl_xor_sync(0xffffffffu, mx0, 2));
        mx1 = fmaxf(mx1, __shfl_xor_sync(0xffffffffu, mx1, 1));
        mx1 = fmaxf(mx1, __shfl_xor_sync(0xffffffffu, mx1, 2));

        const float mn0 = fmaxf(m0, mx0), mn1 = fmaxf(m1, mx1);
        const float corr0 = __expf(m0 - mn0), corr1 = __expf(m1 - mn1);
        m0 = mn0; m1 = mn1;

        float rs0 = 0.f, rs1 = 0.f;
        #pragma unroll
        for (int nf = 0; nf < 8; nf++) {
            sacc[nf][0] = __expf(sacc[nf][0] - mn0);
            sacc[nf][1] = __expf(sacc[nf][1] - mn0);
            sacc[nf][2] = __expf(sacc[nf][2] - mn1);
            sacc[nf][3] = __expf(sacc[nf][3] - mn1);
            rs0 += sacc[nf][0] + sacc[nf][1];
            rs1 += sacc[nf][2] + sacc[nf][3];
        }
        rs0 += __shfl_xor_sync(0xffffffffu, rs0, 1);
        rs0 += __shfl_xor_sync(0xffffffffu, rs0, 2);
        rs1 += __shfl_xor_sync(0xffffffffu, rs1, 1);
        rs1 += __shfl_xor_sync(0xffffffffu, rs1, 2);
        l0 = l0 * corr0 + rs0;
        l1 = l1 * corr1 + rs1;
        #pragma unroll
        for (int nf = 0; nf < 8; nf++) {
            oacc[nf][0] *= corr0; oacc[nf][1] *= corr0;
            oacc[nf][2] *= corr1; oacc[nf][3] *= corr1;
        }

        // O += P V ; P stays in registers (C-fragment == A-fragment layout)
        #pragma unroll
        for (int k4 = 0; k4 < 4; k4++) {
            uint32_t a[4];
            a[0] = packbf(sacc[2 * k4][0],     sacc[2 * k4][1]);
            a[1] = packbf(sacc[2 * k4][2],     sacc[2 * k4][3]);
            a[2] = packbf(sacc[2 * k4 + 1][0], sacc[2 * k4 + 1][1]);
            a[3] = packbf(sacc[2 * k4 + 1][2], sacc[2 * k4 + 1][3]);
            const int kk = k4 * 16;
            #pragma unroll
            for (int np = 0; np < 4; np++) {
                uint32_t r[4];
                const uint32_t addr = sVc +
                    ((kk + (lane & 15)) * LDATT + np * 16 + ((lane >> 4) << 3)) * 2;
                ldsm_x4_t(r, addr);
                mma_bf16(oacc[2 * np],     a, r);
                mma_bf16(oacc[2 * np + 1], a, r + 2);
            }
        }
    }

    const float inv0 = 1.f / l0, inv1 = 1.f / l1;
    #pragma unroll
    for (int nf = 0; nf < 8; nf++) {
        const int c = nf * 8 + 2 * t4;
        *(uint32_t*)&O[base + (size_t)(q0 + rw) * HID + c] =
            packbf(oacc[nf][0] * inv0, oacc[nf][1] * inv0);
        *(uint32_t*)&O[base + (size_t)(q0 + rw + 8) * HID + c] =
            packbf(oacc[nf][2] * inv1, oacc[nf][3] * inv1);
    }
}

// ---------------- launch -------------------------------------------------------
extern "C" void kernel_launch(void* const* d_in, const int* in_sizes, int n_in,
                              void* d_out, int out_size)
{
    const float* x    = (const float*)d_in[0];
    const float* Wq   = (const float*)d_in[1];
    const float* bq   = (const float*)d_in[2];
    const float* Wk   = (const float*)d_in[3];
    const float* bk   = (const float*)d_in[4];
    const float* Wv   = (const float*)d_in[5];
    const float* bv   = (const float*)d_in[6];
    const float* Wo   = (const float*)d_in[7];
    const float* bo   = (const float*)d_in[8];
    const float* ln_g = (const float*)d_in[9];
    const float* ln_b = (const float*)d_in[10];
    float* out = (float*)d_out;

    __nv_bfloat16 *xn_p, *q_p, *k_p, *v_p, *ctx_p, *wqkv_p, *wo_p;
    cudaGetSymbolAddress((void**)&xn_p,   g_xn);
    cudaGetSymbolAddress((void**)&q_p,    g_q);
    cudaGetSymbolAddress((void**)&k_p,    g_k);
    cudaGetSymbolAddress((void**)&v_p,    g_v);
    cudaGetSymbolAddress((void**)&ctx_p,  g_ctx);
    cudaGetSymbolAddress((void**)&wqkv_p, g_wqkv);
    cudaGetSymbolAddress((void**)&wo_p,   g_wo);

    cudaFuncSetAttribute(attn_mma,
        cudaFuncAttributeMaxDynamicSharedMemorySize, SMEM_ATTN);

    // 0) weight conversion fp32 -> bf16
    dim3 cg(1024, 3);
    conv3_kernel<<<cg, 256>>>((const float4*)Wq, (const float4*)Wk,
                              (const float4*)Wv, (__nv_bfloat162*)wqkv_p);
    conv1_kernel<<<1024, 256>>>((const float4*)Wo, (__nv_bfloat162*)wo_p);

    // 1) LayerNorm (bf16 out)
    ln_kernel<<<ROWS, 256>>>(x, ln_g, ln_b, xn_p);

    // 2) fused QKV projection (one GEMM, N=3072)
    dim3 gq(3 * HID / 128, ROWS / 128);
    mma_gemm<<<gq, 256>>>(xn_p, wqkv_p, bq, bk, bv, nullptr,
                          q_p, k_p, v_p, nullptr, 0);

    // 3) attention
    dim3 ag(SEQ / 128, HEADS, BATCH);
    attn_mma<<<ag, 256, SMEM_ATTN>>>(q_p, k_p, v_p, ctx_p);

    // 4) output projection + bias + residual (fp32 out)
    dim3 go(HID / 128, ROWS / 128);
    mma_gemm<<<go, 256>>>(ctx_p, wo_p, bo, bo, bo, x,
                          nullptr, nullptr, nullptr, out, 1);
}

// round 8
// speedup vs baseline: 7.3913x; 1.1228x over previous
#include <cuda_runtime.h>
#include <cuda_bf16.h>
#include <cstdint>

#define HID    1024
#define SEQ    2048
#define BATCH  2
#define HEADS  16
#define HDIM   64
#define ROWS   (BATCH * SEQ)   // 4096

// ---------------- scratch (device globals; no allocations allowed) ----------
__device__ __nv_bfloat16 g_xn  [ROWS * HID];
__device__ __nv_bfloat16 g_q   [ROWS * HID];
__device__ __nv_bfloat16 g_k   [ROWS * HID];
__device__ __nv_bfloat16 g_v   [ROWS * HID];
__device__ __nv_bfloat16 g_ctx [ROWS * HID];
__device__ __nv_bfloat16 g_wqkv[3 * HID * HID];
__device__ __nv_bfloat16 g_wo  [HID * HID];

// ---------------- helpers ----------------------------------------------------
__device__ __forceinline__ uint32_t smem_u32(const void* p) {
    return (uint32_t)__cvta_generic_to_shared(p);
}
__device__ __forceinline__ void cp16(uint32_t dst, const void* src) {
    asm volatile("cp.async.cg.shared.global [%0], [%1], 16;" :: "r"(dst), "l"(src));
}
#define CP_COMMIT() asm volatile("cp.async.commit_group;")
#define CP_WAIT0()  asm volatile("cp.async.wait_group 0;")
#define CP_WAIT1()  asm volatile("cp.async.wait_group 1;")

__device__ __forceinline__ void mma_bf16(float* c, const uint32_t* a, const uint32_t* b) {
    asm volatile(
        "mma.sync.aligned.m16n8k16.row.col.f32.bf16.bf16.f32 "
        "{%0,%1,%2,%3}, {%4,%5,%6,%7}, {%8,%9}, {%0,%1,%2,%3};"
        : "+f"(c[0]), "+f"(c[1]), "+f"(c[2]), "+f"(c[3])
        : "r"(a[0]), "r"(a[1]), "r"(a[2]), "r"(a[3]), "r"(b[0]), "r"(b[1]));
}
__device__ __forceinline__ void ldsm_x4(uint32_t* r, uint32_t addr) {
    asm volatile("ldmatrix.sync.aligned.m8n8.x4.shared.b16 {%0,%1,%2,%3}, [%4];"
        : "=r"(r[0]), "=r"(r[1]), "=r"(r[2]), "=r"(r[3]) : "r"(addr));
}
__device__ __forceinline__ void ldsm_x4_t(uint32_t* r, uint32_t addr) {
    asm volatile("ldmatrix.sync.aligned.m8n8.x4.trans.shared.b16 {%0,%1,%2,%3}, [%4];"
        : "=r"(r[0]), "=r"(r[1]), "=r"(r[2]), "=r"(r[3]) : "r"(addr));
}
__device__ __forceinline__ uint32_t ld32s(const __nv_bfloat16* p) {
    return *(const uint32_t*)p;
}
__device__ __forceinline__ uint32_t packbf(float lo, float hi) {
    __nv_bfloat162 t = __floats2bfloat162_rn(lo, hi);
    return *(uint32_t*)&t;
}

// ---------------- weight convert: fp32 -> bf16 (one launch, 4 matrices) ------
__global__ __launch_bounds__(256) void conv4_kernel(
    const float4* __restrict__ s0, const float4* __restrict__ s1,
    const float4* __restrict__ s2, const float4* __restrict__ s3,
    __nv_bfloat162* __restrict__ dqkv, __nv_bfloat162* __restrict__ dwo)
{
    const int mat = blockIdx.y;
    const float4* src = (mat == 0) ? s0 : (mat == 1) ? s1 : (mat == 2) ? s2 : s3;
    __nv_bfloat162* d = (mat == 3) ? dwo : dqkv + (size_t)mat * (HID * HID / 2);
    const int i = blockIdx.x * 256 + threadIdx.x;
    const float4 v = src[i];
    d[2 * i + 0] = __floats2bfloat162_rn(v.x, v.y);
    d[2 * i + 1] = __floats2bfloat162_rn(v.z, v.w);
}

// ---------------- LayerNorm: one block per row (bf16 out) ---------------------
__global__ __launch_bounds__(256) void ln_kernel(
    const float* __restrict__ x, const float* __restrict__ g,
    const float* __restrict__ b, __nv_bfloat16* __restrict__ xn)
{
    __shared__ float red[16];
    const int row = blockIdx.x;
    const int tid = threadIdx.x;
    const float4 v = *(const float4*)(x + (size_t)row * HID + tid * 4);

    float s1 = v.x + v.y + v.z + v.w;
    float s2 = v.x * v.x + v.y * v.y + v.z * v.z + v.w * v.w;
    #pragma unroll
    for (int off = 16; off; off >>= 1) {
        s1 += __shfl_xor_sync(0xffffffffu, s1, off);
        s2 += __shfl_xor_sync(0xffffffffu, s2, off);
    }
    const int warp = tid >> 5, lane = tid & 31;
    if (lane == 0) { red[warp] = s1; red[warp + 8] = s2; }
    __syncthreads();
    if (tid < 32) {
        float a  = (lane < 8) ? red[lane]     : 0.f;
        float b2 = (lane < 8) ? red[lane + 8] : 0.f;
        #pragma unroll
        for (int off = 4; off; off >>= 1) {
            a  += __shfl_xor_sync(0xffffffffu, a,  off);
            b2 += __shfl_xor_sync(0xffffffffu, b2, off);
        }
        if (lane == 0) { red[0] = a; red[1] = b2; }
    }
    __syncthreads();
    const float mu  = red[0] * (1.f / HID);
    const float var = red[1] * (1.f / HID) - mu * mu;
    const float rs  = rsqrtf(var + 1e-5f);

    const float4 gv = *(const float4*)(g + tid * 4);
    const float4 bv = *(const float4*)(b + tid * 4);
    __nv_bfloat162* o = (__nv_bfloat162*)(xn + (size_t)row * HID + tid * 4);
    o[0] = __floats2bfloat162_rn((v.x - mu) * rs * gv.x + bv.x,
                                 (v.y - mu) * rs * gv.y + bv.y);
    o[1] = __floats2bfloat162_rn((v.z - mu) * rs * gv.z + bv.z,
                                 (v.w - mu) * rs * gv.w + bv.w);
}

// ---------------- bf16 mma GEMM (fused QKV or out-proj) -----------------------
// 128x128x64 k-steps, 8 warps (2x4), warp tile 64x32, m16n8k16,
// 3-stage cp.async pipeline (BK=64), ldmatrix fragment loads. Dynamic smem.
#define LDK   72                       // smem leading dim in halves (144 B rows)
#define TMAT  (128 * LDK)              // halves per matrix per stage
#define TSTG  (2 * TMAT)               // A + B per stage
#define GEMM_SMEM (3 * TSTG * 2)       // bytes = 110592

__global__ __launch_bounds__(256, 2) void mma_gemm(
    const __nv_bfloat16* __restrict__ A, const __nv_bfloat16* __restrict__ W,
    const float* __restrict__ b0p, const float* __restrict__ b1p,
    const float* __restrict__ b2p, const float* __restrict__ resid,
    __nv_bfloat16* __restrict__ C0, __nv_bfloat16* __restrict__ C1,
    __nv_bfloat16* __restrict__ C2, float* __restrict__ Cf, int out_fp32)
{
    extern __shared__ __nv_bfloat16 gsm[];
    const int tid  = threadIdx.x;
    const int lane = tid & 31;
    const int wid  = tid >> 5;
    const int wm   = (wid >> 2) * 64;
    const int wn   = (wid & 3) * 32;
    const int row0 = blockIdx.y * 128, col0 = blockIdx.x * 128;
    const int g    = lane >> 2;
    const int t4   = lane & 3;

    const uint32_t s0 = smem_u32(gsm);

    // fill mapping: 1024 16B-chunks per matrix; 4 per thread per matrix
    const int fr = tid >> 1;                 // base row helper
    (void)fr;
    auto load_chunk = [&](int kc, int stg) {
        const uint32_t sA = s0 + stg * TSTG * 2;
        const uint32_t sB = sA + TMAT * 2;
        const int kcol = kc * 64;
        #pragma unroll
        for (int it = 0; it < 4; it++) {
            const int id = it * 256 + tid;   // 0..1023
            const int r = id >> 3;           // 0..127
            const int c = id & 7;            // 16B chunk
            const uint32_t off = (uint32_t)(r * LDK + c * 8) * 2;
            cp16(sA + off, A + (size_t)(row0 + r) * HID + kcol + c * 8);
            cp16(sB + off, W + (size_t)(col0 + r) * HID + kcol + c * 8);
        }
        CP_COMMIT();
    };

    float acc[4][4][4];
    #pragma unroll
    for (int i = 0; i < 4; i++)
        #pragma unroll
        for (int j = 0; j < 4; j++)
            #pragma unroll
            for (int r = 0; r < 4; r++) acc[i][j][r] = 0.f;

    load_chunk(0, 0);
    load_chunk(1, 1);

    const int arow = (lane & 7) + ((lane >> 3) & 1) * 8;
    const int akof = (lane >> 4) * 8;
    const int brow = (lane & 7) + ((lane >> 4) & 1) * 8;
    const int bkof = ((lane >> 3) & 1) * 8;

    for (int kc = 0; kc < 16; kc++) {
        if (kc < 15) { CP_WAIT1(); } else { CP_WAIT0(); }
        __syncthreads();
        if (kc + 2 < 16) load_chunk(kc + 2, (kc + 2) % 3);

        const uint32_t sAc = s0 + (kc % 3) * TSTG * 2;
        const uint32_t sBc = sAc + TMAT * 2;
        #pragma unroll
        for (int kk = 0; kk < 64; kk += 16) {
            uint32_t af[4][4], bf[2][4];
            #pragma unroll
            for (int mf = 0; mf < 4; mf++)
                ldsm_x4(af[mf], sAc + ((wm + mf * 16 + arow) * LDK + kk + akof) * 2);
            #pragma unroll
            for (int nfp = 0; nfp < 2; nfp++)
                ldsm_x4(bf[nfp], sBc + ((wn + nfp * 16 + brow) * LDK + kk + bkof) * 2);
            #pragma unroll
            for (int mf = 0; mf < 4; mf++)
                #pragma unroll
                for (int nfp = 0; nfp < 2; nfp++) {
                    mma_bf16(acc[mf][2 * nfp],     af[mf], bf[nfp]);
                    mma_bf16(acc[mf][2 * nfp + 1], af[mf], bf[nfp] + 2);
                }
        }
    }

    // epilogue
    const int sel  = col0 >> 10;
    const int colL = col0 & 1023;
    const float* bias = (sel == 0) ? b0p : (sel == 1) ? b1p : b2p;
    __nv_bfloat16* Cb = (sel == 0) ? C0 : (sel == 1) ? C1 : C2;
    const int t2 = t4 * 2;
    #pragma unroll
    for (int mf = 0; mf < 4; mf++) {
        #pragma unroll
        for (int nf = 0; nf < 4; nf++) {
            const int r = row0 + wm + mf * 16 + g;
            const int c = colL + wn + nf * 8 + t2;
            const float2 bb = *(const float2*)&bias[c];
            float o00 = acc[mf][nf][0] + bb.x, o01 = acc[mf][nf][1] + bb.y;
            float o10 = acc[mf][nf][2] + bb.x, o11 = acc[mf][nf][3] + bb.y;
            if (out_fp32) {
                const float2 r0v = *(const float2*)&resid[(size_t)r * HID + c];
                const float2 r1v = *(const float2*)&resid[(size_t)(r + 8) * HID + c];
                float2 a0 = { o00 + r0v.x, o01 + r0v.y };
                float2 a1 = { o10 + r1v.x, o11 + r1v.y };
                *(float2*)&Cf[(size_t)r * HID + c] = a0;
                *(float2*)&Cf[(size_t)(r + 8) * HID + c] = a1;
            } else {
                *(uint32_t*)&Cb[(size_t)r * HID + c] = packbf(o00, o01);
                *(uint32_t*)&Cb[(size_t)(r + 8) * HID + c] = packbf(o10, o11);
            }
        }
    }
}

// ---------------- Flash attention, bf16 mma, register P, 3-stage K/V ---------
#define LDATT 72
#define KVST  (64 * LDATT)
#define SMEM_ATTN ((128 * LDATT + 6 * KVST) * 2)   // 73728 B
#define SM_SCALE 0.18033688011112042f              // 0.125 * log2(e)

__global__ __launch_bounds__(256, 2) void attn_mma(
    const __nv_bfloat16* __restrict__ Q, const __nv_bfloat16* __restrict__ K,
    const __nv_bfloat16* __restrict__ V, __nv_bfloat16* __restrict__ O)
{
    extern __shared__ __nv_bfloat16 sm[];
    __nv_bfloat16* QP = sm;
    __nv_bfloat16* Ks = sm + 128 * LDATT;          // 3 stages
    __nv_bfloat16* Vs = Ks + 3 * KVST;             // 3 stages

    const int tid  = threadIdx.x;
    const int lane = tid & 31;
    const int wid  = tid >> 5;
    const int g    = lane >> 2;
    const int t4   = lane & 3;
    const int q0   = blockIdx.x << 7;
    const size_t base = (size_t)blockIdx.z * SEQ * HID + (size_t)blockIdx.y * HDIM;
    const __nv_bfloat16* Qb = Q + base;
    const __nv_bfloat16* Kb = K + base;
    const __nv_bfloat16* Vb = V + base;
    const int rw = wid * 16 + g;

    const uint32_t sQP = smem_u32(QP);
    const uint32_t sK  = smem_u32(Ks);
    const uint32_t sV  = smem_u32(Vs);

    auto load_kv = [&](int kt, int stg) {
        const int k0n = kt << 6;
        const uint32_t so = stg * KVST * 2;
        const int r = tid >> 2, c = (tid & 3) * 16;
        const __nv_bfloat16* ksrc = Kb + (size_t)(k0n + r) * HID + c;
        const __nv_bfloat16* vsrc = Vb + (size_t)(k0n + r) * HID + c;
        const uint32_t kd = sK + so + (r * LDATT + c) * 2;
        const uint32_t vd = sV + so + (r * LDATT + c) * 2;
        cp16(kd, ksrc); cp16(kd + 16, ksrc + 8);
        cp16(vd, vsrc); cp16(vd + 16, vsrc + 8);
        CP_COMMIT();
    };

    // prologue: group0 = Q + KV(0) ; group1 = KV(1)
    {
        const int r = tid >> 1, c = (tid & 1) * 32;
        const __nv_bfloat16* src = Qb + (size_t)(q0 + r) * HID + c;
        const uint32_t dst = sQP + (r * LDATT + c) * 2;
        cp16(dst, src); cp16(dst + 16, src + 8);
        cp16(dst + 32, src + 16); cp16(dst + 48, src + 24);
    }
    load_kv(0, 0);   // commits group containing Q + KV0
    load_kv(1, 1);

    CP_WAIT1();      // group0 (Q + KV0) done
    __syncthreads();

    uint32_t qf[4][4];
    #pragma unroll
    for (int k4 = 0; k4 < 4; k4++) {
        const int kb = k4 * 16 + 2 * t4;
        qf[k4][0] = ld32s(&QP[rw * LDATT + kb]);
        qf[k4][1] = ld32s(&QP[(rw + 8) * LDATT + kb]);
        qf[k4][2] = ld32s(&QP[rw * LDATT + kb + 8]);
        qf[k4][3] = ld32s(&QP[(rw + 8) * LDATT + kb + 8]);
    }

    float m0 = -1e30f, m1 = -1e30f, l0 = 0.f, l1 = 0.f;
    float oacc[8][4];
    #pragma unroll
    for (int nf = 0; nf < 8; nf++)
        #pragma unroll
        for (int j = 0; j < 4; j++) oacc[nf][j] = 0.f;

    const int brow = (lane & 7) + ((lane >> 4) & 1) * 8;
    const int bkof = ((lane >> 3) & 1) * 8;

    for (int kt = 0; kt < 32; kt++) {
        if (kt < 30) { CP_WAIT1(); } else { CP_WAIT0(); }
        __syncthreads();
        if (kt + 2 < 32) load_kv(kt + 2, (kt + 2) % 3);

        const uint32_t sKc = sK + (kt % 3) * KVST * 2;
        const uint32_t sVc = sV + (kt % 3) * KVST * 2;

        // S = Q K^T (scaled into exp2 domain later)
        float sacc[8][4];
        #pragma unroll
        for (int nf = 0; nf < 8; nf++)
            #pragma unroll
            for (int j = 0; j < 4; j++) sacc[nf][j] = 0.f;

        #pragma unroll
        for (int k4 = 0; k4 < 4; k4++) {
            const int kb0 = k4 * 16;
            #pragma unroll
            for (int nfp = 0; nfp < 4; nfp++) {
                uint32_t bfr[4];
                ldsm_x4(bfr, sKc + ((nfp * 16 + brow) * LDATT + kb0 + bkof) * 2);
                mma_bf16(sacc[2 * nfp],     qf[k4], bfr);
                mma_bf16(sacc[2 * nfp + 1], qf[k4], bfr + 2);
            }
        }

        // online softmax in exp2 domain
        #pragma unroll
        for (int nf = 0; nf < 8; nf++)
            #pragma unroll
            for (int j = 0; j < 4; j++) sacc[nf][j] *= SM_SCALE;

        float mx0 = -1e30f, mx1 = -1e30f;
        #pragma unroll
        for (int nf = 0; nf < 8; nf++) {
            mx0 = fmaxf(mx0, fmaxf(sacc[nf][0], sacc[nf][1]));
            mx1 = fmaxf(mx1, fmaxf(sacc[nf][2], sacc[nf][3]));
        }
        mx0 = fmaxf(mx0, __shfl_xor_sync(0xffffffffu, mx0, 1));
        mx0 = fmaxf(mx0, __shfl_xor_sync(0xffffffffu, mx0, 2));
        mx1 = fmaxf(mx1, __shfl_xor_sync(0xffffffffu, mx1, 1));
        mx1 = fmaxf(mx1, __shfl_xor_sync(0xffffffffu, mx1, 2));

        const float mn0 = fmaxf(m0, mx0), mn1 = fmaxf(m1, mx1);
        const float corr0 = exp2f(m0 - mn0), corr1 = exp2f(m1 - mn1);
        m0 = mn0; m1 = mn1;

        float rs0 = 0.f, rs1 = 0.f;
        #pragma unroll
        for (int nf = 0; nf < 8; nf++) {
            sacc[nf][0] = exp2f(sacc[nf][0] - mn0);
            sacc[nf][1] = exp2f(sacc[nf][1] - mn0);
            sacc[nf][2] = exp2f(sacc[nf][2] - mn1);
            sacc[nf][3] = exp2f(sacc[nf][3] - mn1);
            rs0 += sacc[nf][0] + sacc[nf][1];
            rs1 += sacc[nf][2] + sacc[nf][3];
        }
        rs0 += __shfl_xor_sync(0xffffffffu, rs0, 1);
        rs0 += __shfl_xor_sync(0xffffffffu, rs0, 2);
        rs1 += __shfl_xor_sync(0xffffffffu, rs1, 1);
        rs1 += __shfl_xor_sync(0xffffffffu, rs1, 2);
        l0 = l0 * corr0 + rs0;
        l1 = l1 * corr1 + rs1;
        #pragma unroll
        for (int nf = 0; nf < 8; nf++) {
            oacc[nf][0] *= corr0; oacc[nf][1] *= corr0;
            oacc[nf][2] *= corr1; oacc[nf][3] *= corr1;
        }

        // O += P V ; P stays in registers
        #pragma unroll
        for (int k4 = 0; k4 < 4; k4++) {
            uint32_t a[4];
            a[0] = packbf(sacc[2 * k4][0],     sacc[2 * k4][1]);
            a[1] = packbf(sacc[2 * k4][2],     sacc[2 * k4][3]);
            a[2] = packbf(sacc[2 * k4 + 1][0], sacc[2 * k4 + 1][1]);
            a[3] = packbf(sacc[2 * k4 + 1][2], sacc[2 * k4 + 1][3]);
            const int kk = k4 * 16;
            #pragma unroll
            for (int np = 0; np < 4; np++) {
                uint32_t r[4];
                const uint32_t addr = sVc +
                    ((kk + (lane & 15)) * LDATT + np * 16 + ((lane >> 4) << 3)) * 2;
                ldsm_x4_t(r, addr);
                mma_bf16(oacc[2 * np],     a, r);
                mma_bf16(oacc[2 * np + 1], a, r + 2);
            }
        }
    }

    const float inv0 = 1.f / l0, inv1 = 1.f / l1;
    #pragma unroll
    for (int nf = 0; nf < 8; nf++) {
        const int c = nf * 8 + 2 * t4;
        *(uint32_t*)&O[base + (size_t)(q0 + rw) * HID + c] =
            packbf(oacc[nf][0] * inv0, oacc[nf][1] * inv0);
        *(uint32_t*)&O[base + (size_t)(q0 + rw + 8) * HID + c] =
            packbf(oacc[nf][2] * inv1, oacc[nf][3] * inv1);
    }
}

// ---------------- launch -------------------------------------------------------
extern "C" void kernel_launch(void* const* d_in, const int* in_sizes, int n_in,
                              void* d_out, int out_size)
{
    const float* x    = (const float*)d_in[0];
    const float* Wq   = (const float*)d_in[1];
    const float* bq   = (const float*)d_in[2];
    const float* Wk   = (const float*)d_in[3];
    const float* bk   = (const float*)d_in[4];
    const float* Wv   = (const float*)d_in[5];
    const float* bv   = (const float*)d_in[6];
    const float* Wo   = (const float*)d_in[7];
    const float* bo   = (const float*)d_in[8];
    const float* ln_g = (const float*)d_in[9];
    const float* ln_b = (const float*)d_in[10];
    float* out = (float*)d_out;

    __nv_bfloat16 *xn_p, *q_p, *k_p, *v_p, *ctx_p, *wqkv_p, *wo_p;
    cudaGetSymbolAddress((void**)&xn_p,   g_xn);
    cudaGetSymbolAddress((void**)&q_p,    g_q);
    cudaGetSymbolAddress((void**)&k_p,    g_k);
    cudaGetSymbolAddress((void**)&v_p,    g_v);
    cudaGetSymbolAddress((void**)&ctx_p,  g_ctx);
    cudaGetSymbolAddress((void**)&wqkv_p, g_wqkv);
    cudaGetSymbolAddress((void**)&wo_p,   g_wo);

    cudaFuncSetAttribute(attn_mma,
        cudaFuncAttributeMaxDynamicSharedMemorySize, SMEM_ATTN);
    cudaFuncSetAttribute(mma_gemm,
        cudaFuncAttributeMaxDynamicSharedMemorySize, GEMM_SMEM);

    // 0) weight conversion fp32 -> bf16 (single launch)
    dim3 cg(1024, 4);
    conv4_kernel<<<cg, 256>>>((const float4*)Wq, (const float4*)Wk,
                              (const float4*)Wv, (const float4*)Wo,
                              (__nv_bfloat162*)wqkv_p, (__nv_bfloat162*)wo_p);

    // 1) LayerNorm (bf16 out)
    ln_kernel<<<ROWS, 256>>>(x, ln_g, ln_b, xn_p);

    // 2) fused QKV projection (one GEMM, N=3072)
    dim3 gq(3 * HID / 128, ROWS / 128);
    mma_gemm<<<gq, 256, GEMM_SMEM>>>(xn_p, wqkv_p, bq, bk, bv, nullptr,
                                     q_p, k_p, v_p, nullptr, 0);

    // 3) attention
    dim3 ag(SEQ / 128, HEADS, BATCH);
    attn_mma<<<ag, 256, SMEM_ATTN>>>(q_p, k_p, v_p, ctx_p);

    // 4) output projection + bias + residual (fp32 out)
    dim3 go(HID / 128, ROWS / 128);
    mma_gemm<<<go, 256, GEMM_SMEM>>>(ctx_p, wo_p, bo, bo, bo, x,
                                     nullptr, nullptr, nullptr, out, 1);
}

// round 9
// speedup vs baseline: 7.6376x; 1.0333x over previous
#include <cuda_runtime.h>
#include <cuda_bf16.h>
#include <cstdint>

#define HID    1024
#define SEQ    2048
#define BATCH  2
#define HEADS  16
#define HDIM   64
#define ROWS   (BATCH * SEQ)   // 4096

// ---------------- scratch (device globals; no allocations allowed) ----------
__device__ __nv_bfloat16 g_xn  [ROWS * HID];
__device__ __nv_bfloat16 g_q   [ROWS * HID];
__device__ __nv_bfloat16 g_k   [ROWS * HID];
__device__ __nv_bfloat16 g_v   [ROWS * HID];
__device__ __nv_bfloat16 g_ctx [ROWS * HID];
__device__ __nv_bfloat16 g_wqkv[3 * HID * HID];
__device__ __nv_bfloat16 g_wo  [HID * HID];

// ---------------- helpers ----------------------------------------------------
__device__ __forceinline__ uint32_t smem_u32(const void* p) {
    return (uint32_t)__cvta_generic_to_shared(p);
}
__device__ __forceinline__ void cp16(uint32_t dst, const void* src) {
    asm volatile("cp.async.cg.shared.global [%0], [%1], 16;" :: "r"(dst), "l"(src));
}
#define CP_COMMIT() asm volatile("cp.async.commit_group;")
#define CP_WAIT0()  asm volatile("cp.async.wait_group 0;")
#define CP_WAIT1()  asm volatile("cp.async.wait_group 1;")

__device__ __forceinline__ void mma_bf16(float* c, const uint32_t* a, const uint32_t* b) {
    asm volatile(
        "mma.sync.aligned.m16n8k16.row.col.f32.bf16.bf16.f32 "
        "{%0,%1,%2,%3}, {%4,%5,%6,%7}, {%8,%9}, {%0,%1,%2,%3};"
        : "+f"(c[0]), "+f"(c[1]), "+f"(c[2]), "+f"(c[3])
        : "r"(a[0]), "r"(a[1]), "r"(a[2]), "r"(a[3]), "r"(b[0]), "r"(b[1]));
}
__device__ __forceinline__ void ldsm_x4(uint32_t* r, uint32_t addr) {
    asm volatile("ldmatrix.sync.aligned.m8n8.x4.shared.b16 {%0,%1,%2,%3}, [%4];"
        : "=r"(r[0]), "=r"(r[1]), "=r"(r[2]), "=r"(r[3]) : "r"(addr));
}
__device__ __forceinline__ void ldsm_x4_t(uint32_t* r, uint32_t addr) {
    asm volatile("ldmatrix.sync.aligned.m8n8.x4.trans.shared.b16 {%0,%1,%2,%3}, [%4];"
        : "=r"(r[0]), "=r"(r[1]), "=r"(r[2]), "=r"(r[3]) : "r"(addr));
}
__device__ __forceinline__ uint32_t ld32s(const __nv_bfloat16* p) {
    return *(const uint32_t*)p;
}
__device__ __forceinline__ uint32_t packbf(float lo, float hi) {
    __nv_bfloat162 t = __floats2bfloat162_rn(lo, hi);
    return *(uint32_t*)&t;
}
__device__ __forceinline__ float ex2(float x) {
    float y;
    asm("ex2.approx.ftz.f32 %0, %1;" : "=f"(y) : "f"(x));
    return y;
}

// ---------------- fused weight-convert + LayerNorm ----------------------------
// grid (4096, 2): y==0 -> LN row blockIdx.x ; y==1 -> weight conversion
__global__ __launch_bounds__(256) void prep_kernel(
    const float* __restrict__ x, const float* __restrict__ lg,
    const float* __restrict__ lb, __nv_bfloat16* __restrict__ xn,
    const float4* __restrict__ s0, const float4* __restrict__ s1,
    const float4* __restrict__ s2, const float4* __restrict__ s3,
    __nv_bfloat162* __restrict__ dqkv, __nv_bfloat162* __restrict__ dwo)
{
    const int tid = threadIdx.x;
    if (blockIdx.y == 1) {
        const int i = blockIdx.x * 256 + tid;         // 0..1048575
        const int mat = i >> 18;                      // 262144 float4 per matrix
        const int j = i & 262143;
        const float4* src = (mat == 0) ? s0 : (mat == 1) ? s1 : (mat == 2) ? s2 : s3;
        __nv_bfloat162* d = (mat == 3) ? dwo : dqkv + (size_t)mat * (HID * HID / 2);
        const float4 v = src[j];
        d[2 * j + 0] = __floats2bfloat162_rn(v.x, v.y);
        d[2 * j + 1] = __floats2bfloat162_rn(v.z, v.w);
        return;
    }
    __shared__ float red[16];
    const int row = blockIdx.x;
    const float4 v = *(const float4*)(x + (size_t)row * HID + tid * 4);

    float s1v = v.x + v.y + v.z + v.w;
    float s2v = v.x * v.x + v.y * v.y + v.z * v.z + v.w * v.w;
    #pragma unroll
    for (int off = 16; off; off >>= 1) {
        s1v += __shfl_xor_sync(0xffffffffu, s1v, off);
        s2v += __shfl_xor_sync(0xffffffffu, s2v, off);
    }
    const int warp = tid >> 5, lane = tid & 31;
    if (lane == 0) { red[warp] = s1v; red[warp + 8] = s2v; }
    __syncthreads();
    if (tid < 32) {
        float a  = (lane < 8) ? red[lane]     : 0.f;
        float b2 = (lane < 8) ? red[lane + 8] : 0.f;
        #pragma unroll
        for (int off = 4; off; off >>= 1) {
            a  += __shfl_xor_sync(0xffffffffu, a,  off);
            b2 += __shfl_xor_sync(0xffffffffu, b2, off);
        }
        if (lane == 0) { red[0] = a; red[1] = b2; }
    }
    __syncthreads();
    const float mu  = red[0] * (1.f / HID);
    const float var = red[1] * (1.f / HID) - mu * mu;
    const float rs  = rsqrtf(var + 1e-5f);

    const float4 gv = *(const float4*)(lg + tid * 4);
    const float4 bv = *(const float4*)(lb + tid * 4);
    __nv_bfloat162* o = (__nv_bfloat162*)(xn + (size_t)row * HID + tid * 4);
    o[0] = __floats2bfloat162_rn((v.x - mu) * rs * gv.x + bv.x,
                                 (v.y - mu) * rs * gv.y + bv.y);
    o[1] = __floats2bfloat162_rn((v.z - mu) * rs * gv.z + bv.z,
                                 (v.w - mu) * rs * gv.w + bv.w);
}

// ---------------- bf16 mma GEMM (fused QKV or out-proj) -----------------------
// 128x128x64 k-steps, 8 warps (2x4), warp tile 64x32, m16n8k16,
// 3-stage cp.async pipeline (BK=64), ldmatrix fragment loads. Dynamic smem.
#define LDK   72                       // smem leading dim in halves (144 B rows)
#define TMAT  (128 * LDK)              // halves per matrix per stage
#define TSTG  (2 * TMAT)               // A + B per stage
#define GEMM_SMEM (3 * TSTG * 2)       // bytes = 110592

__global__ __launch_bounds__(256, 2) void mma_gemm(
    const __nv_bfloat16* __restrict__ A, const __nv_bfloat16* __restrict__ W,
    const float* __restrict__ b0p, const float* __restrict__ b1p,
    const float* __restrict__ b2p, const float* __restrict__ resid,
    __nv_bfloat16* __restrict__ C0, __nv_bfloat16* __restrict__ C1,
    __nv_bfloat16* __restrict__ C2, float* __restrict__ Cf, int out_fp32)
{
    extern __shared__ __nv_bfloat16 gsm[];
    const int tid  = threadIdx.x;
    const int lane = tid & 31;
    const int wid  = tid >> 5;
    const int wm   = (wid >> 2) * 64;
    const int wn   = (wid & 3) * 32;
    const int row0 = blockIdx.y * 128, col0 = blockIdx.x * 128;
    const int g    = lane >> 2;
    const int t4   = lane & 3;

    const uint32_t s0 = smem_u32(gsm);

    auto load_chunk = [&](int kc, int stg) {
        const uint32_t sA = s0 + stg * TSTG * 2;
        const uint32_t sB = sA + TMAT * 2;
        const int kcol = kc * 64;
        #pragma unroll
        for (int it = 0; it < 4; it++) {
            const int id = it * 256 + tid;   // 0..1023
            const int r = id >> 3;           // 0..127
            const int c = id & 7;            // 16B chunk
            const uint32_t off = (uint32_t)(r * LDK + c * 8) * 2;
            cp16(sA + off, A + (size_t)(row0 + r) * HID + kcol + c * 8);
            cp16(sB + off, W + (size_t)(col0 + r) * HID + kcol + c * 8);
        }
        CP_COMMIT();
    };

    float acc[4][4][4];
    #pragma unroll
    for (int i = 0; i < 4; i++)
        #pragma unroll
        for (int j = 0; j < 4; j++)
            #pragma unroll
            for (int r = 0; r < 4; r++) acc[i][j][r] = 0.f;

    load_chunk(0, 0);
    load_chunk(1, 1);

    const int arow = (lane & 7) + ((lane >> 3) & 1) * 8;
    const int akof = (lane >> 4) * 8;
    const int brow = (lane & 7) + ((lane >> 4) & 1) * 8;
    const int bkof = ((lane >> 3) & 1) * 8;

    for (int kc = 0; kc < 16; kc++) {
        if (kc < 15) { CP_WAIT1(); } else { CP_WAIT0(); }
        __syncthreads();
        if (kc + 2 < 16) load_chunk(kc + 2, (kc + 2) % 3);

        const uint32_t sAc = s0 + (kc % 3) * TSTG * 2;
        const uint32_t sBc = sAc + TMAT * 2;
        #pragma unroll
        for (int kk = 0; kk < 64; kk += 16) {
            uint32_t af[4][4], bf[2][4];
            #pragma unroll
            for (int mf = 0; mf < 4; mf++)
                ldsm_x4(af[mf], sAc + ((wm + mf * 16 + arow) * LDK + kk + akof) * 2);
            #pragma unroll
            for (int nfp = 0; nfp < 2; nfp++)
                ldsm_x4(bf[nfp], sBc + ((wn + nfp * 16 + brow) * LDK + kk + bkof) * 2);
            #pragma unroll
            for (int mf = 0; mf < 4; mf++)
                #pragma unroll
                for (int nfp = 0; nfp < 2; nfp++) {
                    mma_bf16(acc[mf][2 * nfp],     af[mf], bf[nfp]);
                    mma_bf16(acc[mf][2 * nfp + 1], af[mf], bf[nfp] + 2);
                }
        }
    }

    // epilogue
    const int sel  = col0 >> 10;
    const int colL = col0 & 1023;
    const float* bias = (sel == 0) ? b0p : (sel == 1) ? b1p : b2p;
    __nv_bfloat16* Cb = (sel == 0) ? C0 : (sel == 1) ? C1 : C2;
    const int t2 = t4 * 2;
    #pragma unroll
    for (int mf = 0; mf < 4; mf++) {
        #pragma unroll
        for (int nf = 0; nf < 4; nf++) {
            const int r = row0 + wm + mf * 16 + g;
            const int c = colL + wn + nf * 8 + t2;
            const float2 bb = *(const float2*)&bias[c];
            float o00 = acc[mf][nf][0] + bb.x, o01 = acc[mf][nf][1] + bb.y;
            float o10 = acc[mf][nf][2] + bb.x, o11 = acc[mf][nf][3] + bb.y;
            if (out_fp32) {
                const float2 r0v = *(const float2*)&resid[(size_t)r * HID + c];
                const float2 r1v = *(const float2*)&resid[(size_t)(r + 8) * HID + c];
                float2 a0 = { o00 + r0v.x, o01 + r0v.y };
                float2 a1 = { o10 + r1v.x, o11 + r1v.y };
                *(float2*)&Cf[(size_t)r * HID + c] = a0;
                *(float2*)&Cf[(size_t)(r + 8) * HID + c] = a1;
            } else {
                *(uint32_t*)&Cb[(size_t)r * HID + c] = packbf(o00, o01);
                *(uint32_t*)&Cb[(size_t)(r + 8) * HID + c] = packbf(o10, o11);
            }
        }
    }
}

// ---------------- Flash attention: chunked softmax, 3-stage K/V ---------------
#define LDATT 72
#define KVST  (64 * LDATT)
#define SMEM_ATTN ((128 * LDATT + 6 * KVST) * 2)   // 73728 B
#define SM_SCALE 0.18033688011112042f              // 0.125 * log2(e)

__global__ __launch_bounds__(256, 2) void attn_mma(
    const __nv_bfloat16* __restrict__ Q, const __nv_bfloat16* __restrict__ K,
    const __nv_bfloat16* __restrict__ V, __nv_bfloat16* __restrict__ O)
{
    extern __shared__ __nv_bfloat16 sm[];
    __nv_bfloat16* QP = sm;
    __nv_bfloat16* Ks = sm + 128 * LDATT;          // 3 stages
    __nv_bfloat16* Vs = Ks + 3 * KVST;             // 3 stages

    const int tid  = threadIdx.x;
    const int lane = tid & 31;
    const int wid  = tid >> 5;
    const int g    = lane >> 2;
    const int t4   = lane & 3;
    const int q0   = blockIdx.x << 7;
    const size_t base = (size_t)blockIdx.z * SEQ * HID + (size_t)blockIdx.y * HDIM;
    const __nv_bfloat16* Qb = Q + base;
    const __nv_bfloat16* Kb = K + base;
    const __nv_bfloat16* Vb = V + base;
    const int rw = wid * 16 + g;

    const uint32_t sQP = smem_u32(QP);
    const uint32_t sK  = smem_u32(Ks);
    const uint32_t sV  = smem_u32(Vs);

    auto load_kv = [&](int kt, int stg) {
        const int k0n = kt << 6;
        const uint32_t so = stg * KVST * 2;
        const int r = tid >> 2, c = (tid & 3) * 16;
        const __nv_bfloat16* ksrc = Kb + (size_t)(k0n + r) * HID + c;
        const __nv_bfloat16* vsrc = Vb + (size_t)(k0n + r) * HID + c;
        const uint32_t kd = sK + so + (r * LDATT + c) * 2;
        const uint32_t vd = sV + so + (r * LDATT + c) * 2;
        cp16(kd, ksrc); cp16(kd + 16, ksrc + 8);
        cp16(vd, vsrc); cp16(vd + 16, vsrc + 8);
        CP_COMMIT();
    };

    {
        const int r = tid >> 1, c = (tid & 1) * 32;
        const __nv_bfloat16* src = Qb + (size_t)(q0 + r) * HID + c;
        const uint32_t dst = sQP + (r * LDATT + c) * 2;
        cp16(dst, src); cp16(dst + 16, src + 8);
        cp16(dst + 32, src + 16); cp16(dst + 48, src + 24);
    }
    load_kv(0, 0);
    load_kv(1, 1);

    CP_WAIT1();
    __syncthreads();

    uint32_t qf[4][4];
    #pragma unroll
    for (int k4 = 0; k4 < 4; k4++) {
        const int kb = k4 * 16 + 2 * t4;
        qf[k4][0] = ld32s(&QP[rw * LDATT + kb]);
        qf[k4][1] = ld32s(&QP[(rw + 8) * LDATT + kb]);
        qf[k4][2] = ld32s(&QP[rw * LDATT + kb + 8]);
        qf[k4][3] = ld32s(&QP[(rw + 8) * LDATT + kb + 8]);
    }

    float m0 = -1e30f, m1 = -1e30f, l0 = 0.f, l1 = 0.f;
    float oacc[8][4];
    #pragma unroll
    for (int nf = 0; nf < 8; nf++)
        #pragma unroll
        for (int j = 0; j < 4; j++) oacc[nf][j] = 0.f;

    const int brow = (lane & 7) + ((lane >> 4) & 1) * 8;
    const int bkof = ((lane >> 3) & 1) * 8;

    for (int kt = 0; kt < 32; kt++) {
        if (kt < 30) { CP_WAIT1(); } else { CP_WAIT0(); }
        __syncthreads();
        if (kt + 2 < 32) load_kv(kt + 2, (kt + 2) % 3);

        const uint32_t sKc = sK + (kt % 3) * KVST * 2;
        const uint32_t sVc = sV + (kt % 3) * KVST * 2;

        // S = Q K^T over all 64 keys (raw logits)
        float sacc[8][4];
        #pragma unroll
        for (int nf = 0; nf < 8; nf++)
            #pragma unroll
            for (int j = 0; j < 4; j++) sacc[nf][j] = 0.f;

        #pragma unroll
        for (int k4 = 0; k4 < 4; k4++) {
            const int kb0 = k4 * 16;
            #pragma unroll
            for (int nfp = 0; nfp < 4; nfp++) {
                uint32_t bfr[4];
                ldsm_x4(bfr, sKc + ((nfp * 16 + brow) * LDATT + kb0 + bkof) * 2);
                mma_bf16(sacc[2 * nfp],     qf[k4], bfr);
                mma_bf16(sacc[2 * nfp + 1], qf[k4], bfr + 2);
            }
        }

        // two 32-key chunks: softmax(chunk) then PV(chunk); the PV tensor
        // burst of chunk A overlaps issue of chunk B's softmax.
        #pragma unroll
        for (int ch = 0; ch < 2; ch++) {
            const int nfb = ch * 4;            // sacc groups nfb..nfb+3
            float mx0 = -1e30f, mx1 = -1e30f;
            #pragma unroll
            for (int nf = nfb; nf < nfb + 4; nf++) {
                mx0 = fmaxf(mx0, fmaxf(sacc[nf][0], sacc[nf][1]));
                mx1 = fmaxf(mx1, fmaxf(sacc[nf][2], sacc[nf][3]));
            }
            mx0 = fmaxf(mx0, __shfl_xor_sync(0xffffffffu, mx0, 1));
            mx0 = fmaxf(mx0, __shfl_xor_sync(0xffffffffu, mx0, 2));
            mx1 = fmaxf(mx1, __shfl_xor_sync(0xffffffffu, mx1, 1));
            mx1 = fmaxf(mx1, __shfl_xor_sync(0xffffffffu, mx1, 2));

            const float mn0 = fmaxf(m0, mx0 * SM_SCALE);
            const float mn1 = fmaxf(m1, mx1 * SM_SCALE);
            const float corr0 = ex2(m0 - mn0), corr1 = ex2(m1 - mn1);
            m0 = mn0; m1 = mn1;

            float rs0 = 0.f, rs1 = 0.f;
            #pragma unroll
            for (int nf = nfb; nf < nfb + 4; nf++) {
                sacc[nf][0] = ex2(fmaf(sacc[nf][0], SM_SCALE, -mn0));
                sacc[nf][1] = ex2(fmaf(sacc[nf][1], SM_SCALE, -mn0));
                sacc[nf][2] = ex2(fmaf(sacc[nf][2], SM_SCALE, -mn1));
                sacc[nf][3] = ex2(fmaf(sacc[nf][3], SM_SCALE, -mn1));
                rs0 += sacc[nf][0] + sacc[nf][1];
                rs1 += sacc[nf][2] + sacc[nf][3];
            }
            rs0 += __shfl_xor_sync(0xffffffffu, rs0, 1);
            rs0 += __shfl_xor_sync(0xffffffffu, rs0, 2);
            rs1 += __shfl_xor_sync(0xffffffffu, rs1, 1);
            rs1 += __shfl_xor_sync(0xffffffffu, rs1, 2);
            l0 = l0 * corr0 + rs0;
            l1 = l1 * corr1 + rs1;
            #pragma unroll
            for (int nf = 0; nf < 8; nf++) {
                oacc[nf][0] *= corr0; oacc[nf][1] *= corr0;
                oacc[nf][2] *= corr1; oacc[nf][3] *= corr1;
            }

            // PV for this chunk's 32 keys (k4 = 2*ch, 2*ch+1)
            #pragma unroll
            for (int kh = 0; kh < 2; kh++) {
                const int k4 = 2 * ch + kh;
                uint32_t a[4];
                a[0] = packbf(sacc[2 * k4][0],     sacc[2 * k4][1]);
                a[1] = packbf(sacc[2 * k4][2],     sacc[2 * k4][3]);
                a[2] = packbf(sacc[2 * k4 + 1][0], sacc[2 * k4 + 1][1]);
                a[3] = packbf(sacc[2 * k4 + 1][2], sacc[2 * k4 + 1][3]);
                const int kk = k4 * 16;
                #pragma unroll
                for (int np = 0; np < 4; np++) {
                    uint32_t r[4];
                    const uint32_t addr = sVc +
                        ((kk + (lane & 15)) * LDATT + np * 16 + ((lane >> 4) << 3)) * 2;
                    ldsm_x4_t(r, addr);
                    mma_bf16(oacc[2 * np],     a, r);
                    mma_bf16(oacc[2 * np + 1], a, r + 2);
                }
            }
        }
    }

    const float inv0 = 1.f / l0, inv1 = 1.f / l1;
    #pragma unroll
    for (int nf = 0; nf < 8; nf++) {
        const int c = nf * 8 + 2 * t4;
        *(uint32_t*)&O[base + (size_t)(q0 + rw) * HID + c] =
            packbf(oacc[nf][0] * inv0, oacc[nf][1] * inv0);
        *(uint32_t*)&O[base + (size_t)(q0 + rw + 8) * HID + c] =
            packbf(oacc[nf][2] * inv1, oacc[nf][3] * inv1);
    }
}

// ---------------- launch -------------------------------------------------------
extern "C" void kernel_launch(void* const* d_in, const int* in_sizes, int n_in,
                              void* d_out, int out_size)
{
    const float* x    = (const float*)d_in[0];
    const float* Wq   = (const float*)d_in[1];
    const float* bq   = (const float*)d_in[2];
    const float* Wk   = (const float*)d_in[3];
    const float* bk   = (const float*)d_in[4];
    const float* Wv   = (const float*)d_in[5];
    const float* bv   = (const float*)d_in[6];
    const float* Wo   = (const float*)d_in[7];
    const float* bo   = (const float*)d_in[8];
    const float* ln_g = (const float*)d_in[9];
    const float* ln_b = (const float*)d_in[10];
    float* out = (float*)d_out;

    __nv_bfloat16 *xn_p, *q_p, *k_p, *v_p, *ctx_p, *wqkv_p, *wo_p;
    cudaGetSymbolAddress((void**)&xn_p,   g_xn);
    cudaGetSymbolAddress((void**)&q_p,    g_q);
    cudaGetSymbolAddress((void**)&k_p,    g_k);
    cudaGetSymbolAddress((void**)&v_p,    g_v);
    cudaGetSymbolAddress((void**)&ctx_p,  g_ctx);
    cudaGetSymbolAddress((void**)&wqkv_p, g_wqkv);
    cudaGetSymbolAddress((void**)&wo_p,   g_wo);

    cudaFuncSetAttribute(attn_mma,
        cudaFuncAttributeMaxDynamicSharedMemorySize, SMEM_ATTN);
    cudaFuncSetAttribute(mma_gemm,
        cudaFuncAttributeMaxDynamicSharedMemorySize, GEMM_SMEM);

    // 0) fused LayerNorm + weight conversion
    dim3 pg(4096, 2);
    prep_kernel<<<pg, 256>>>(x, ln_g, ln_b, xn_p,
                             (const float4*)Wq, (const float4*)Wk,
                             (const float4*)Wv, (const float4*)Wo,
                             (__nv_bfloat162*)wqkv_p, (__nv_bfloat162*)wo_p);

    // 1) fused QKV projection (one GEMM, N=3072)
    dim3 gq(3 * HID / 128, ROWS / 128);
    mma_gemm<<<gq, 256, GEMM_SMEM>>>(xn_p, wqkv_p, bq, bk, bv, nullptr,
                                     q_p, k_p, v_p, nullptr, 0);

    // 2) attention
    dim3 ag(SEQ / 128, HEADS, BATCH);
    attn_mma<<<ag, 256, SMEM_ATTN>>>(q_p, k_p, v_p, ctx_p);

    // 3) output projection + bias + residual (fp32 out)
    dim3 go(HID / 128, ROWS / 128);
    mma_gemm<<<go, 256, GEMM_SMEM>>>(ctx_p, wo_p, bo, bo, bo, x,
                                     nullptr, nullptr, nullptr, out, 1);
}

// round 11
// speedup vs baseline: 7.6878x; 1.0066x over previous
#include <cuda_runtime.h>
#include <cuda_bf16.h>
#include <cstdint>

#define HID    1024
#define SEQ    2048
#define BATCH  2
#define HEADS  16
#define HDIM   64
#define ROWS   (BATCH * SEQ)   // 4096

// ---------------- scratch (device globals; no allocations allowed) ----------
__device__ __nv_bfloat16 g_xn  [ROWS * HID];
__device__ __nv_bfloat16 g_q   [ROWS * HID];
__device__ __nv_bfloat16 g_k   [ROWS * HID];
__device__ __nv_bfloat16 g_v   [ROWS * HID];
__device__ __nv_bfloat16 g_ctx [ROWS * HID];
__device__ __nv_bfloat16 g_wqkv[3 * HID * HID];
__device__ __nv_bfloat16 g_wo  [HID * HID];

// ---------------- helpers ----------------------------------------------------
__device__ __forceinline__ uint32_t smem_u32(const void* p) {
    return (uint32_t)__cvta_generic_to_shared(p);
}
__device__ __forceinline__ void cp16(uint32_t dst, const void* src) {
    asm volatile("cp.async.cg.shared.global [%0], [%1], 16;" :: "r"(dst), "l"(src));
}
#define CP_COMMIT() asm volatile("cp.async.commit_group;")
#define CP_WAIT0()  asm volatile("cp.async.wait_group 0;")
#define CP_WAIT1()  asm volatile("cp.async.wait_group 1;")

__device__ __forceinline__ void mma_bf16(float* c, const uint32_t* a, const uint32_t* b) {
    asm volatile(
        "mma.sync.aligned.m16n8k16.row.col.f32.bf16.bf16.f32 "
        "{%0,%1,%2,%3}, {%4,%5,%6,%7}, {%8,%9}, {%0,%1,%2,%3};"
        : "+f"(c[0]), "+f"(c[1]), "+f"(c[2]), "+f"(c[3])
        : "r"(a[0]), "r"(a[1]), "r"(a[2]), "r"(a[3]), "r"(b[0]), "r"(b[1]));
}
__device__ __forceinline__ void ldsm_x4(uint32_t* r, uint32_t addr) {
    asm volatile("ldmatrix.sync.aligned.m8n8.x4.shared.b16 {%0,%1,%2,%3}, [%4];"
        : "=r"(r[0]), "=r"(r[1]), "=r"(r[2]), "=r"(r[3]) : "r"(addr));
}
__device__ __forceinline__ void ldsm_x4_t(uint32_t* r, uint32_t addr) {
    asm volatile("ldmatrix.sync.aligned.m8n8.x4.trans.shared.b16 {%0,%1,%2,%3}, [%4];"
        : "=r"(r[0]), "=r"(r[1]), "=r"(r[2]), "=r"(r[3]) : "r"(addr));
}
__device__ __forceinline__ uint32_t ld32s(const __nv_bfloat16* p) {
    return *(const uint32_t*)p;
}
__device__ __forceinline__ uint32_t packbf(float lo, float hi) {
    __nv_bfloat162 t = __floats2bfloat162_rn(lo, hi);
    return *(uint32_t*)&t;
}
__device__ __forceinline__ float ex2(float x) {
    float y;
    asm("ex2.approx.ftz.f32 %0, %1;" : "=f"(y) : "f"(x));
    return y;
}
// ---- mbarrier helpers --------------------------------------------------------
__device__ __forceinline__ void mb_init(uint32_t mbar, uint32_t cnt) {
    asm volatile("mbarrier.init.shared.b64 [%0], %1;" :: "r"(mbar), "r"(cnt) : "memory");
}
__device__ __forceinline__ void mb_arrive(uint32_t mbar) {
    asm volatile("mbarrier.arrive.shared.b64 _, [%0];" :: "r"(mbar) : "memory");
}
__device__ __forceinline__ void cp_async_mb_arrive(uint32_t mbar) {
    // .noinc: arrival counts against the init count (inc-form is self-neutralizing)
    asm volatile("cp.async.mbarrier.arrive.noinc.shared.b64 [%0];" :: "r"(mbar) : "memory");
}
__device__ __forceinline__ void mb_wait(uint32_t mbar, uint32_t parity) {
    asm volatile(
        "{\n\t.reg .pred P;\n\t"
        "W_%=:\n\t"
        "mbarrier.try_wait.parity.acquire.cta.shared::cta.b64 P, [%0], %1, 0x989680;\n\t"
        "@P bra D_%=;\n\t"
        "bra W_%=;\n\t"
        "D_%=:\n\t}"
        :: "r"(mbar), "r"(parity) : "memory");
}

// ---------------- fused weight-convert + LayerNorm ----------------------------
__global__ __launch_bounds__(256) void prep_kernel(
    const float* __restrict__ x, const float* __restrict__ lg,
    const float* __restrict__ lb, __nv_bfloat16* __restrict__ xn,
    const float4* __restrict__ s0, const float4* __restrict__ s1,
    const float4* __restrict__ s2, const float4* __restrict__ s3,
    __nv_bfloat162* __restrict__ dqkv, __nv_bfloat162* __restrict__ dwo)
{
    const int tid = threadIdx.x;
    if (blockIdx.y == 1) {
        const int i = blockIdx.x * 256 + tid;
        const int mat = i >> 18;
        const int j = i & 262143;
        const float4* src = (mat == 0) ? s0 : (mat == 1) ? s1 : (mat == 2) ? s2 : s3;
        __nv_bfloat162* d = (mat == 3) ? dwo : dqkv + (size_t)mat * (HID * HID / 2);
        const float4 v = src[j];
        d[2 * j + 0] = __floats2bfloat162_rn(v.x, v.y);
        d[2 * j + 1] = __floats2bfloat162_rn(v.z, v.w);
        return;
    }
    __shared__ float red[16];
    const int row = blockIdx.x;
    const float4 v = *(const float4*)(x + (size_t)row * HID + tid * 4);

    float s1v = v.x + v.y + v.z + v.w;
    float s2v = v.x * v.x + v.y * v.y + v.z * v.z + v.w * v.w;
    #pragma unroll
    for (int off = 16; off; off >>= 1) {
        s1v += __shfl_xor_sync(0xffffffffu, s1v, off);
        s2v += __shfl_xor_sync(0xffffffffu, s2v, off);
    }
    const int warp = tid >> 5, lane = tid & 31;
    if (lane == 0) { red[warp] = s1v; red[warp + 8] = s2v; }
    __syncthreads();
    if (tid < 32) {
        float a  = (lane < 8) ? red[lane]     : 0.f;
        float b2 = (lane < 8) ? red[lane + 8] : 0.f;
        #pragma unroll
        for (int off = 4; off; off >>= 1) {
            a  += __shfl_xor_sync(0xffffffffu, a,  off);
            b2 += __shfl_xor_sync(0xffffffffu, b2, off);
        }
        if (lane == 0) { red[0] = a; red[1] = b2; }
    }
    __syncthreads();
    const float mu  = red[0] * (1.f / HID);
    const float var = red[1] * (1.f / HID) - mu * mu;
    const float rs  = rsqrtf(var + 1e-5f);

    const float4 gv = *(const float4*)(lg + tid * 4);
    const float4 bv = *(const float4*)(lb + tid * 4);
    __nv_bfloat162* o = (__nv_bfloat162*)(xn + (size_t)row * HID + tid * 4);
    o[0] = __floats2bfloat162_rn((v.x - mu) * rs * gv.x + bv.x,
                                 (v.y - mu) * rs * gv.y + bv.y);
    o[1] = __floats2bfloat162_rn((v.z - mu) * rs * gv.z + bv.z,
                                 (v.w - mu) * rs * gv.w + bv.w);
}

// ---------------- bf16 mma GEMM (fused QKV or out-proj) -----------------------
#define LDK   72
#define TMAT  (128 * LDK)
#define TSTG  (2 * TMAT)
#define GEMM_SMEM (3 * TSTG * 2)

__global__ __launch_bounds__(256, 2) void mma_gemm(
    const __nv_bfloat16* __restrict__ A, const __nv_bfloat16* __restrict__ W,
    const float* __restrict__ b0p, const float* __restrict__ b1p,
    const float* __restrict__ b2p, const float* __restrict__ resid,
    __nv_bfloat16* __restrict__ C0, __nv_bfloat16* __restrict__ C1,
    __nv_bfloat16* __restrict__ C2, float* __restrict__ Cf, int out_fp32)
{
    extern __shared__ __nv_bfloat16 gsm[];
    const int tid  = threadIdx.x;
    const int lane = tid & 31;
    const int wid  = tid >> 5;
    const int wm   = (wid >> 2) * 64;
    const int wn   = (wid & 3) * 32;
    const int row0 = blockIdx.y * 128, col0 = blockIdx.x * 128;
    const int g    = lane >> 2;
    const int t4   = lane & 3;

    const uint32_t s0 = smem_u32(gsm);

    auto load_chunk = [&](int kc, int stg) {
        const uint32_t sA = s0 + stg * TSTG * 2;
        const uint32_t sB = sA + TMAT * 2;
        const int kcol = kc * 64;
        #pragma unroll
        for (int it = 0; it < 4; it++) {
            const int id = it * 256 + tid;
            const int r = id >> 3;
            const int c = id & 7;
            const uint32_t off = (uint32_t)(r * LDK + c * 8) * 2;
            cp16(sA + off, A + (size_t)(row0 + r) * HID + kcol + c * 8);
            cp16(sB + off, W + (size_t)(col0 + r) * HID + kcol + c * 8);
        }
        CP_COMMIT();
    };

    float acc[4][4][4];
    #pragma unroll
    for (int i = 0; i < 4; i++)
        #pragma unroll
        for (int j = 0; j < 4; j++)
            #pragma unroll
            for (int r = 0; r < 4; r++) acc[i][j][r] = 0.f;

    load_chunk(0, 0);
    load_chunk(1, 1);

    const int arow = (lane & 7) + ((lane >> 3) & 1) * 8;
    const int akof = (lane >> 4) * 8;
    const int brow = (lane & 7) + ((lane >> 4) & 1) * 8;
    const int bkof = ((lane >> 3) & 1) * 8;

    for (int kc = 0; kc < 16; kc++) {
        if (kc < 15) { CP_WAIT1(); } else { CP_WAIT0(); }
        __syncthreads();
        if (kc + 2 < 16) load_chunk(kc + 2, (kc + 2) % 3);

        const uint32_t sAc = s0 + (kc % 3) * TSTG * 2;
        const uint32_t sBc = sAc + TMAT * 2;
        #pragma unroll
        for (int kk = 0; kk < 64; kk += 16) {
            uint32_t af[4][4], bf[2][4];
            #pragma unroll
            for (int mf = 0; mf < 4; mf++)
                ldsm_x4(af[mf], sAc + ((wm + mf * 16 + arow) * LDK + kk + akof) * 2);
            #pragma unroll
            for (int nfp = 0; nfp < 2; nfp++)
                ldsm_x4(bf[nfp], sBc + ((wn + nfp * 16 + brow) * LDK + kk + bkof) * 2);
            #pragma unroll
            for (int mf = 0; mf < 4; mf++)
                #pragma unroll
                for (int nfp = 0; nfp < 2; nfp++) {
                    mma_bf16(acc[mf][2 * nfp],     af[mf], bf[nfp]);
                    mma_bf16(acc[mf][2 * nfp + 1], af[mf], bf[nfp] + 2);
                }
        }
    }

    const int sel  = col0 >> 10;
    const int colL = col0 & 1023;
    const float* bias = (sel == 0) ? b0p : (sel == 1) ? b1p : b2p;
    __nv_bfloat16* Cb = (sel == 0) ? C0 : (sel == 1) ? C1 : C2;
    const int t2 = t4 * 2;
    #pragma unroll
    for (int mf = 0; mf < 4; mf++) {
        #pragma unroll
        for (int nf = 0; nf < 4; nf++) {
            const int r = row0 + wm + mf * 16 + g;
            const int c = colL + wn + nf * 8 + t2;
            const float2 bb = *(const float2*)&bias[c];
            float o00 = acc[mf][nf][0] + bb.x, o01 = acc[mf][nf][1] + bb.y;
            float o10 = acc[mf][nf][2] + bb.x, o11 = acc[mf][nf][3] + bb.y;
            if (out_fp32) {
                const float2 r0v = *(const float2*)&resid[(size_t)r * HID + c];
                const float2 r1v = *(const float2*)&resid[(size_t)(r + 8) * HID + c];
                float2 a0 = { o00 + r0v.x, o01 + r0v.y };
                float2 a1 = { o10 + r1v.x, o11 + r1v.y };
                *(float2*)&Cf[(size_t)r * HID + c] = a0;
                *(float2*)&Cf[(size_t)(r + 8) * HID + c] = a1;
            } else {
                *(uint32_t*)&Cb[(size_t)r * HID + c] = packbf(o00, o01);
                *(uint32_t*)&Cb[(size_t)(r + 8) * HID + c] = packbf(o10, o11);
            }
        }
    }
}

// ---------------- Flash attention: mbarrier free-running pipeline -------------
#define LDATT 72
#define NSTG  4
#define KVST  (64 * LDATT)
#define SMEM_ATTN ((128 * LDATT + 2 * NSTG * KVST) * 2)   // 92160 B
#define SM_SCALE 0.18033688011112042f                     // 0.125 * log2(e)

__global__ __launch_bounds__(256, 2) void attn_mma(
    const __nv_bfloat16* __restrict__ Q, const __nv_bfloat16* __restrict__ K,
    const __nv_bfloat16* __restrict__ V, __nv_bfloat16* __restrict__ O)
{
    extern __shared__ __nv_bfloat16 sm[];
    __nv_bfloat16* QP = sm;
    __nv_bfloat16* Ks = sm + 128 * LDATT;          // NSTG stages
    __nv_bfloat16* Vs = Ks + NSTG * KVST;          // NSTG stages
    __shared__ uint64_t mbars[2 * NSTG];           // full[0..3], empty[0..3]

    const int tid  = threadIdx.x;
    const int lane = tid & 31;
    const int wid  = tid >> 5;
    const int g    = lane >> 2;
    const int t4   = lane & 3;
    const int q0   = blockIdx.x << 7;
    const size_t base = (size_t)blockIdx.z * SEQ * HID + (size_t)blockIdx.y * HDIM;
    const __nv_bfloat16* Qb = Q + base;
    const __nv_bfloat16* Kb = K + base;
    const __nv_bfloat16* Vb = V + base;
    const int rw = wid * 16 + g;

    const uint32_t sQP = smem_u32(QP);
    const uint32_t sK  = smem_u32(Ks);
    const uint32_t sV  = smem_u32(Vs);
    const uint32_t mb  = smem_u32(mbars);
    // full(s) = mb + s*8 ; empty(s) = mb + 32 + s*8

    if (tid == 0) {
        #pragma unroll
        for (int s = 0; s < NSTG; s++) {
            mb_init(mb + s * 8, 256);        // full: one .noinc arrive per thread
            mb_init(mb + 32 + s * 8, 8);     // empty: one arrive per warp
        }
    }
    __syncthreads();

    auto load_kv = [&](int kt, int stg) {
        const int k0n = kt << 6;
        const uint32_t so = (uint32_t)stg * KVST * 2;
        const int r = tid >> 2, c = (tid & 3) * 16;
        const __nv_bfloat16* ksrc = Kb + (size_t)(k0n + r) * HID + c;
        const __nv_bfloat16* vsrc = Vb + (size_t)(k0n + r) * HID + c;
        const uint32_t kd = sK + so + (r * LDATT + c) * 2;
        const uint32_t vd = sV + so + (r * LDATT + c) * 2;
        cp16(kd, ksrc); cp16(kd + 16, ksrc + 8);
        cp16(vd, vsrc); cp16(vd + 16, vsrc + 8);
        cp_async_mb_arrive(mb + stg * 8);
    };

    // prologue: Q (covered by full[0]) + tiles 0..2 into stages 0..2
    {
        const int r = tid >> 1, c = (tid & 1) * 32;
        const __nv_bfloat16* src = Qb + (size_t)(q0 + r) * HID + c;
        const uint32_t dst = sQP + (r * LDATT + c) * 2;
        cp16(dst, src); cp16(dst + 16, src + 8);
        cp16(dst + 32, src + 16); cp16(dst + 48, src + 24);
    }
    load_kv(0, 0);
    load_kv(1, 1);
    load_kv(2, 2);

    mb_wait(mb + 0, 0);   // Q + tile 0 resident

    uint32_t qf[4][4];
    #pragma unroll
    for (int k4 = 0; k4 < 4; k4++) {
        const int kb = k4 * 16 + 2 * t4;
        qf[k4][0] = ld32s(&QP[rw * LDATT + kb]);
        qf[k4][1] = ld32s(&QP[(rw + 8) * LDATT + kb]);
        qf[k4][2] = ld32s(&QP[rw * LDATT + kb + 8]);
        qf[k4][3] = ld32s(&QP[(rw + 8) * LDATT + kb + 8]);
    }

    float m0 = -1e30f, m1 = -1e30f, l0 = 0.f, l1 = 0.f;
    float oacc[8][4];
    #pragma unroll
    for (int nf = 0; nf < 8; nf++)
        #pragma unroll
        for (int j = 0; j < 4; j++) oacc[nf][j] = 0.f;

    const int brow = (lane & 7) + ((lane >> 4) & 1) * 8;
    const int bkof = ((lane >> 3) & 1) * 8;

    int cph = 0;   // consumer phase
    int pph = 0;   // producer phase

    for (int kt = 0; kt < 32; kt++) {
        // producer: prefetch tile kt+3 into the stage freed by tile kt-1
        {
            const int tp = kt + 3;
            if (tp < 32) {
                const int ps = tp & 3;
                if (tp > 3) mb_wait(mb + 32 + ps * 8, pph);
                load_kv(tp, ps);
                if (tp > 3 && ps == 3) pph ^= 1;
            }
        }

        // consumer: wait data for tile kt
        const int cs = kt & 3;
        mb_wait(mb + cs * 8, cph);

        const uint32_t sKc = sK + (uint32_t)cs * KVST * 2;
        const uint32_t sVc = sV + (uint32_t)cs * KVST * 2;

        float sacc[8][4];
        #pragma unroll
        for (int nf = 0; nf < 8; nf++)
            #pragma unroll
            for (int j = 0; j < 4; j++) sacc[nf][j] = 0.f;

        #pragma unroll
        for (int k4 = 0; k4 < 4; k4++) {
            const int kb0 = k4 * 16;
            #pragma unroll
            for (int nfp = 0; nfp < 4; nfp++) {
                uint32_t bfr[4];
                ldsm_x4(bfr, sKc + ((nfp * 16 + brow) * LDATT + kb0 + bkof) * 2);
                mma_bf16(sacc[2 * nfp],     qf[k4], bfr);
                mma_bf16(sacc[2 * nfp + 1], qf[k4], bfr + 2);
            }
        }

        // chunked online softmax + PV (two 32-key chunks)
        #pragma unroll
        for (int ch = 0; ch < 2; ch++) {
            const int nfb = ch * 4;
            float mx0 = -1e30f, mx1 = -1e30f;
            #pragma unroll
            for (int nf = nfb; nf < nfb + 4; nf++) {
                mx0 = fmaxf(mx0, fmaxf(sacc[nf][0], sacc[nf][1]));
                mx1 = fmaxf(mx1, fmaxf(sacc[nf][2], sacc[nf][3]));
            }
            mx0 = fmaxf(mx0, __shfl_xor_sync(0xffffffffu, mx0, 1));
            mx0 = fmaxf(mx0, __shfl_xor_sync(0xffffffffu, mx0, 2));
            mx1 = fmaxf(mx1, __shfl_xor_sync(0xffffffffu, mx1, 1));
            mx1 = fmaxf(mx1, __shfl_xor_sync(0xffffffffu, mx1, 2));

            const float mn0 = fmaxf(m0, mx0 * SM_SCALE);
            const float mn1 = fmaxf(m1, mx1 * SM_SCALE);
            const float corr0 = ex2(m0 - mn0), corr1 = ex2(m1 - mn1);
            m0 = mn0; m1 = mn1;

            float rs0 = 0.f, rs1 = 0.f;
            #pragma unroll
            for (int nf = nfb; nf < nfb + 4; nf++) {
                sacc[nf][0] = ex2(fmaf(sacc[nf][0], SM_SCALE, -mn0));
                sacc[nf][1] = ex2(fmaf(sacc[nf][1], SM_SCALE, -mn0));
                sacc[nf][2] = ex2(fmaf(sacc[nf][2], SM_SCALE, -mn1));
                sacc[nf][3] = ex2(fmaf(sacc[nf][3], SM_SCALE, -mn1));
                rs0 += sacc[nf][0] + sacc[nf][1];
                rs1 += sacc[nf][2] + sacc[nf][3];
            }
            rs0 += __shfl_xor_sync(0xffffffffu, rs0, 1);
            rs0 += __shfl_xor_sync(0xffffffffu, rs0, 2);
            rs1 += __shfl_xor_sync(0xffffffffu, rs1, 1);
            rs1 += __shfl_xor_sync(0xffffffffu, rs1, 2);
            l0 = l0 * corr0 + rs0;
            l1 = l1 * corr1 + rs1;
            #pragma unroll
            for (int nf = 0; nf < 8; nf++) {
                oacc[nf][0] *= corr0; oacc[nf][1] *= corr0;
                oacc[nf][2] *= corr1; oacc[nf][3] *= corr1;
            }

            #pragma unroll
            for (int kh = 0; kh < 2; kh++) {
                const int k4 = 2 * ch + kh;
                uint32_t a[4];
                a[0] = packbf(sacc[2 * k4][0],     sacc[2 * k4][1]);
                a[1] = packbf(sacc[2 * k4][2],     sacc[2 * k4][3]);
                a[2] = packbf(sacc[2 * k4 + 1][0], sacc[2 * k4 + 1][1]);
                a[3] = packbf(sacc[2 * k4 + 1][2], sacc[2 * k4 + 1][3]);
                const int kk = k4 * 16;
                #pragma unroll
                for (int np = 0; np < 4; np++) {
                    uint32_t r[4];
                    const uint32_t addr = sVc +
                        ((kk + (lane & 15)) * LDATT + np * 16 + ((lane >> 4) << 3)) * 2;
                    ldsm_x4_t(r, addr);
                    mma_bf16(oacc[2 * np],     a, r);
                    mma_bf16(oacc[2 * np + 1], a, r + 2);
                }
            }
        }

        // stage cs consumed by this warp
        if (lane == 0) mb_arrive(mb + 32 + cs * 8);
        if (cs == 3) cph ^= 1;
    }

    const float inv0 = 1.f / l0, inv1 = 1.f / l1;
    #pragma unroll
    for (int nf = 0; nf < 8; nf++) {
        const int c = nf * 8 + 2 * t4;
        *(uint32_t*)&O[base + (size_t)(q0 + rw) * HID + c] =
            packbf(oacc[nf][0] * inv0, oacc[nf][1] * inv0);
        *(uint32_t*)&O[base + (size_t)(q0 + rw + 8) * HID + c] =
            packbf(oacc[nf][2] * inv1, oacc[nf][3] * inv1);
    }
}

// ---------------- launch -------------------------------------------------------
extern "C" void kernel_launch(void* const* d_in, const int* in_sizes, int n_in,
                              void* d_out, int out_size)
{
    const float* x    = (const float*)d_in[0];
    const float* Wq   = (const float*)d_in[1];
    const float* bq   = (const float*)d_in[2];
    const float* Wk   = (const float*)d_in[3];
    const float* bk   = (const float*)d_in[4];
    const float* Wv   = (const float*)d_in[5];
    const float* bv   = (const float*)d_in[6];
    const float* Wo   = (const float*)d_in[7];
    const float* bo   = (const float*)d_in[8];
    const float* ln_g = (const float*)d_in[9];
    const float* ln_b = (const float*)d_in[10];
    float* out = (float*)d_out;

    __nv_bfloat16 *xn_p, *q_p, *k_p, *v_p, *ctx_p, *wqkv_p, *wo_p;
    cudaGetSymbolAddress((void**)&xn_p,   g_xn);
    cudaGetSymbolAddress((void**)&q_p,    g_q);
    cudaGetSymbolAddress((void**)&k_p,    g_k);
    cudaGetSymbolAddress((void**)&v_p,    g_v);
    cudaGetSymbolAddress((void**)&ctx_p,  g_ctx);
    cudaGetSymbolAddress((void**)&wqkv_p, g_wqkv);
    cudaGetSymbolAddress((void**)&wo_p,   g_wo);

    cudaFuncSetAttribute(attn_mma,
        cudaFuncAttributeMaxDynamicSharedMemorySize, SMEM_ATTN);
    cudaFuncSetAttribute(mma_gemm,
        cudaFuncAttributeMaxDynamicSharedMemorySize, GEMM_SMEM);

    // 0) fused LayerNorm + weight conversion
    dim3 pg(4096, 2);
    prep_kernel<<<pg, 256>>>(x, ln_g, ln_b, xn_p,
                             (const float4*)Wq, (const float4*)Wk,
                             (const float4*)Wv, (const float4*)Wo,
                             (__nv_bfloat162*)wqkv_p, (__nv_bfloat162*)wo_p);

    // 1) fused QKV projection (one GEMM, N=3072)
    dim3 gq(3 * HID / 128, ROWS / 128);
    mma_gemm<<<gq, 256, GEMM_SMEM>>>(xn_p, wqkv_p, bq, bk, bv, nullptr,
                                     q_p, k_p, v_p, nullptr, 0);

    // 2) attention (free-running mbarrier pipeline)
    dim3 ag(SEQ / 128, HEADS, BATCH);
    attn_mma<<<ag, 256, SMEM_ATTN>>>(q_p, k_p, v_p, ctx_p);

    // 3) output projection + bias + residual (fp32 out)
    dim3 go(HID / 128, ROWS / 128);
    mma_gemm<<<go, 256, GEMM_SMEM>>>(ctx_p, wo_p, bo, bo, bo, x,
                                     nullptr, nullptr, nullptr, out, 1);
}